// round 2
// baseline (speedup 1.0000x reference)
#include <cuda_runtime.h>
#include <math.h>

#define D1 256
#define C2 40
#define MAXN 50176
#define MAXE 800000
#define MAXET (MAXE + MAXN)

// ---------------- static scratch (no runtime allocation) ----------------
__device__ float g_xl1[(size_t)MAXN * D1];
__device__ float g_xr1[(size_t)MAXN * D1];
__device__ float g_h1 [(size_t)MAXN * D1];
__device__ float g_h2 [(size_t)MAXN * D1];
__device__ float g_xl2[(size_t)MAXN * C2];
__device__ float g_xr2[(size_t)MAXN * C2];
__device__ float g_e1 [(size_t)MAXET * 4];
__device__ float g_e2 [MAXET];
__device__ int   g_counts[MAXN + 1];
__device__ int   g_offs  [MAXN + 1];
__device__ int   g_cursor[MAXN + 1];
__device__ int   g_src[MAXET];
__device__ int   g_eid[MAXET];
__device__ float g_bn[512];

// ---------------- zero counts + bn accumulators ----------------
__global__ void k_zero(int n) {
    int i = blockIdx.x * blockDim.x + threadIdx.x;
    if (i <= n) g_counts[i] = 0;
    if (i < 512) g_bn[i] = 0.f;
}

// ---------------- CSR build ----------------
__global__ void k_count(const int* __restrict__ ei, int E, int N) {
    int i = blockIdx.x * blockDim.x + threadIdx.x;
    if (i >= E + N) return;
    int dst = (i < E) ? ei[E + i] : (i - E);
    atomicAdd(&g_counts[dst], 1);
}

__global__ void k_scan(int n) {
    __shared__ int sh[1024];
    __shared__ int s_carry;
    int t = threadIdx.x;
    if (t == 0) s_carry = 0;
    __syncthreads();
    for (int base = 0; base < n; base += 1024) {
        int v = (base + t < n) ? g_counts[base + t] : 0;
        sh[t] = v;
        __syncthreads();
        for (int off = 1; off < 1024; off <<= 1) {
            int y = (t >= off) ? sh[t - off] : 0;
            __syncthreads();
            sh[t] += y;
            __syncthreads();
        }
        int out = s_carry + sh[t] - v;   // exclusive
        if (base + t < n) { g_offs[base + t] = out; g_cursor[base + t] = out; }
        __syncthreads();
        if (t == 0) s_carry += sh[1023];
        __syncthreads();
    }
    if (t == 0) g_offs[n] = s_carry;
}

__global__ void k_fill(const int* __restrict__ ei, int E, int N) {
    int i = blockIdx.x * blockDim.x + threadIdx.x;
    if (i >= E + N) return;
    int src, dst;
    if (i < E) { src = ei[i]; dst = ei[E + i]; } else { src = dst = i - E; }
    int p = atomicAdd(&g_cursor[dst], 1);
    g_src[p] = src;
    g_eid[p] = i;
}

// ---------------- generic tiled SGEMM: C[M,N] = A[M,K] @ B[K,N] ----------------
__global__ __launch_bounds__(256) void k_gemm(
    const float* __restrict__ A, const float* __restrict__ B,
    float* __restrict__ C, int M, int N, int K)
{
    __shared__ float As[16][64];
    __shared__ float Bs[16][68];
    int tid = threadIdx.x;
    int tx = tid & 15, ty = tid >> 4;
    int m0 = blockIdx.y * 64, n0 = blockIdx.x * 64;
    float acc[4][4] = {};
    for (int k0 = 0; k0 < K; k0 += 16) {
#pragma unroll
        for (int i = 0; i < 4; i++) {
            int idx = i * 256 + tid;
            int r = idx >> 4, c = idx & 15;
            float v = 0.f;
            int gr = m0 + r;
            if (gr < M) v = A[(size_t)gr * K + k0 + c];
            As[c][r] = v;
        }
#pragma unroll
        for (int i = 0; i < 4; i++) {
            int idx = i * 256 + tid;
            int r = idx >> 6, c = idx & 63;
            float v = 0.f;
            int gc = n0 + c;
            if (gc < N) v = B[(size_t)(k0 + r) * N + gc];
            Bs[r][c] = v;
        }
        __syncthreads();
#pragma unroll
        for (int kk = 0; kk < 16; kk++) {
            float a[4], b[4];
#pragma unroll
            for (int i = 0; i < 4; i++) a[i] = As[kk][ty * 4 + i];
#pragma unroll
            for (int j = 0; j < 4; j++) b[j] = Bs[kk][tx * 4 + j];
#pragma unroll
            for (int i = 0; i < 4; i++)
#pragma unroll
                for (int j = 0; j < 4; j++) acc[i][j] += a[i] * b[j];
        }
        __syncthreads();
    }
#pragma unroll
    for (int i = 0; i < 4; i++) {
        int gr = m0 + ty * 4 + i;
        if (gr >= M) continue;
#pragma unroll
        for (int j = 0; j < 4; j++) {
            int gc = n0 + tx * 4 + j;
            if (gc < N) C[(size_t)gr * N + gc] = acc[i][j];
        }
    }
}

// ---------------- layer-1 edge logits: warp per edge ----------------
__global__ __launch_bounds__(256) void k_logits1(const int* __restrict__ ei,
                                                 const float* __restrict__ att,
                                                 int E, int N)
{
    int gt = blockIdx.x * blockDim.x + threadIdx.x;
    int w = gt >> 5, lane = gt & 31;
    if (w >= E + N) return;
    int src, dst;
    if (w < E) { src = ei[w]; dst = ei[E + w]; } else { src = dst = w - E; }
    const float4* pl = (const float4*)g_xl1 + (size_t)src * 64 + lane * 2;
    const float4* pr = (const float4*)g_xr1 + (size_t)dst * 64 + lane * 2;
    const float4* pa = (const float4*)att + lane * 2;
    float s = 0.f;
#pragma unroll
    for (int q = 0; q < 2; q++) {
        float4 a = pl[q], b = pr[q], w4 = pa[q];
        float v;
        v = a.x + b.x; s += fmaxf(v, 0.2f * v) * w4.x;
        v = a.y + b.y; s += fmaxf(v, 0.2f * v) * w4.y;
        v = a.z + b.z; s += fmaxf(v, 0.2f * v) * w4.z;
        v = a.w + b.w; s += fmaxf(v, 0.2f * v) * w4.w;
    }
    s += __shfl_down_sync(0xffffffffu, s, 4, 8);
    s += __shfl_down_sync(0xffffffffu, s, 2, 8);
    s += __shfl_down_sync(0xffffffffu, s, 1, 8);
    if ((lane & 7) == 0) g_e1[(size_t)w * 4 + (lane >> 3)] = s;
}

// ---------------- layer-1 softmax + aggregate: warp per dst node ----------------
__global__ __launch_bounds__(256) void k_agg1(const float* __restrict__ b1, int N)
{
    int gt = blockIdx.x * blockDim.x + threadIdx.x;
    int w = gt >> 5, lane = gt & 31;
    if (w >= N) return;
    int beg = g_offs[w], end = g_offs[w + 1];

    float mx0 = -1e30f, mx1 = -1e30f, mx2 = -1e30f, mx3 = -1e30f;
    for (int p = beg + lane; p < end; p += 32) {
        float4 ev = ((const float4*)g_e1)[g_eid[p]];
        mx0 = fmaxf(mx0, ev.x); mx1 = fmaxf(mx1, ev.y);
        mx2 = fmaxf(mx2, ev.z); mx3 = fmaxf(mx3, ev.w);
    }
#pragma unroll
    for (int off = 16; off; off >>= 1) {
        mx0 = fmaxf(mx0, __shfl_xor_sync(0xffffffffu, mx0, off));
        mx1 = fmaxf(mx1, __shfl_xor_sync(0xffffffffu, mx1, off));
        mx2 = fmaxf(mx2, __shfl_xor_sync(0xffffffffu, mx2, off));
        mx3 = fmaxf(mx3, __shfl_xor_sync(0xffffffffu, mx3, off));
    }
    float dn0 = 0.f, dn1 = 0.f, dn2 = 0.f, dn3 = 0.f;
    for (int p = beg + lane; p < end; p += 32) {
        float4 ev = ((const float4*)g_e1)[g_eid[p]];
        dn0 += expf(ev.x - mx0); dn1 += expf(ev.y - mx1);
        dn2 += expf(ev.z - mx2); dn3 += expf(ev.w - mx3);
    }
#pragma unroll
    for (int off = 16; off; off >>= 1) {
        dn0 += __shfl_xor_sync(0xffffffffu, dn0, off);
        dn1 += __shfl_xor_sync(0xffffffffu, dn1, off);
        dn2 += __shfl_xor_sync(0xffffffffu, dn2, off);
        dn3 += __shfl_xor_sync(0xffffffffu, dn3, off);
    }
    int head = lane >> 3;
    float m  = (lane < 16) ? ((lane < 8) ? mx0 : mx1) : ((lane < 24) ? mx2 : mx3);
    float dd = (lane < 16) ? ((lane < 8) ? dn0 : dn1) : ((lane < 24) ? dn2 : dn3);
    float inv = 1.f / (dd + 1e-16f);

    float acc0 = 0, acc1 = 0, acc2 = 0, acc3 = 0, acc4 = 0, acc5 = 0, acc6 = 0, acc7 = 0;
    for (int p = beg; p < end; p++) {
        int eid = g_eid[p], src = g_src[p];
        float ev = g_e1[(size_t)eid * 4 + head];
        float al = expf(ev - m) * inv;
        const float4* px = (const float4*)g_xl1 + (size_t)src * 64 + lane * 2;
        float4 a0 = px[0], a1 = px[1];
        acc0 += al * a0.x; acc1 += al * a0.y; acc2 += al * a0.z; acc3 += al * a0.w;
        acc4 += al * a1.x; acc5 += al * a1.y; acc6 += al * a1.z; acc7 += al * a1.w;
    }
    const float4* pb = (const float4*)b1 + lane * 2;
    float4 bb0 = pb[0], bb1 = pb[1];
    float4 o0 = make_float4(acc0 + bb0.x, acc1 + bb0.y, acc2 + bb0.z, acc3 + bb0.w);
    float4 o1 = make_float4(acc4 + bb1.x, acc5 + bb1.y, acc6 + bb1.z, acc7 + bb1.w);
    ((float4*)g_h1)[(size_t)w * 64 + lane * 2 + 0] = o0;
    ((float4*)g_h1)[(size_t)w * 64 + lane * 2 + 1] = o1;
}

// ---------------- batch-norm stats ----------------
__global__ __launch_bounds__(256) void k_bnstats(int N)
{
    int c = threadIdx.x;           // 256 columns
    int r0 = blockIdx.x * 128;
    int rend = min(r0 + 128, N);
    float s = 0.f, s2 = 0.f;
    for (int r = r0; r < rend; r++) {
        float v = g_h1[(size_t)r * 256 + c];
        s += v; s2 += v * v;
    }
    atomicAdd(&g_bn[c], s);
    atomicAdd(&g_bn[256 + c], s2);
}

// ---------------- batch-norm apply + ELU ----------------
__global__ __launch_bounds__(256) void k_bnapply(const float* __restrict__ gamma,
                                                 const float* __restrict__ beta, int N)
{
    int i = blockIdx.x * blockDim.x + threadIdx.x;
    int total = N * 256;
    if (i >= total) return;
    int c = i & 255;
    float invN = 1.f / (float)N;
    float mu = g_bn[c] * invN;
    float var = g_bn[256 + c] * invN - mu * mu;
    float rs = rsqrtf(var + 1e-5f);
    float v = gamma[c] * (g_h1[i] - mu) * rs + beta[c];
    g_h2[i] = v > 0.f ? v : expm1f(v);
}

// ---------------- layer-2 edge logits: warp per edge ----------------
__global__ __launch_bounds__(256) void k_logits2(const int* __restrict__ ei,
                                                 const float* __restrict__ att2,
                                                 int E, int N)
{
    int gt = blockIdx.x * blockDim.x + threadIdx.x;
    int w = gt >> 5, lane = gt & 31;
    if (w >= E + N) return;
    int src, dst;
    if (w < E) { src = ei[w]; dst = ei[E + w]; } else { src = dst = w - E; }
    float v = g_xl2[(size_t)src * 40 + lane] + g_xr2[(size_t)dst * 40 + lane];
    float s = fmaxf(v, 0.2f * v) * att2[lane];
    if (lane < 8) {
        int c = 32 + lane;
        float v2 = g_xl2[(size_t)src * 40 + c] + g_xr2[(size_t)dst * 40 + c];
        s += fmaxf(v2, 0.2f * v2) * att2[c];
    }
#pragma unroll
    for (int off = 16; off; off >>= 1) s += __shfl_xor_sync(0xffffffffu, s, off);
    if (lane == 0) g_e2[w] = s;
}

// ---------------- layer-2 softmax + aggregate: warp per dst node ----------------
__global__ __launch_bounds__(256) void k_agg2(const float* __restrict__ b2,
                                              float* __restrict__ out, int N)
{
    int gt = blockIdx.x * blockDim.x + threadIdx.x;
    int w = gt >> 5, lane = gt & 31;
    if (w >= N) return;
    int beg = g_offs[w], end = g_offs[w + 1];

    float mx = -1e30f;
    for (int p = beg + lane; p < end; p += 32) mx = fmaxf(mx, g_e2[g_eid[p]]);
#pragma unroll
    for (int off = 16; off; off >>= 1) mx = fmaxf(mx, __shfl_xor_sync(0xffffffffu, mx, off));
    float dn = 0.f;
    for (int p = beg + lane; p < end; p += 32) dn += expf(g_e2[g_eid[p]] - mx);
#pragma unroll
    for (int off = 16; off; off >>= 1) dn += __shfl_xor_sync(0xffffffffu, dn, off);
    float inv = 1.f / (dn + 1e-16f);

    float a0 = 0.f, a1 = 0.f;
    for (int p = beg; p < end; p++) {
        int eid = g_eid[p], src = g_src[p];
        float al = expf(g_e2[eid] - mx) * inv;
        a0 += al * g_xl2[(size_t)src * 40 + lane];
        if (lane < 8) a1 += al * g_xl2[(size_t)src * 40 + 32 + lane];
    }
    out[(size_t)w * 40 + lane] = a0 + b2[lane];
    if (lane < 8) out[(size_t)w * 40 + 32 + lane] = a1 + b2[32 + lane];
}

// ---------------- host launcher ----------------
extern "C" void kernel_launch(void* const* d_in, const int* in_sizes, int n_in,
                              void* d_out, int out_size)
{
    const float* x      = (const float*)d_in[0];
    const int*   ei     = (const int*)  d_in[1];
    const float* Wl1    = (const float*)d_in[2];
    const float* Wr1    = (const float*)d_in[3];
    const float* att1   = (const float*)d_in[4];
    const float* b1     = (const float*)d_in[5];
    const float* gamma1 = (const float*)d_in[6];
    const float* beta1  = (const float*)d_in[7];
    const float* Wl2    = (const float*)d_in[8];
    const float* Wr2    = (const float*)d_in[9];
    const float* att2   = (const float*)d_in[10];
    const float* b2     = (const float*)d_in[11];
    float* out = (float*)d_out;

    int N = in_sizes[0] / 128;
    int E = in_sizes[1] / 2;
    int ET = E + N;

    void *pxl1, *pxr1, *ph2, *pxl2, *pxr2;
    cudaGetSymbolAddress(&pxl1, g_xl1);
    cudaGetSymbolAddress(&pxr1, g_xr1);
    cudaGetSymbolAddress(&ph2,  g_h2);
    cudaGetSymbolAddress(&pxl2, g_xl2);
    cudaGetSymbolAddress(&pxr2, g_xr2);

    k_zero<<<(N + 256) / 256, 256>>>(N);
    k_count<<<(ET + 255) / 256, 256>>>(ei, E, N);
    k_scan<<<1, 1024>>>(N);
    k_fill<<<(ET + 255) / 256, 256>>>(ei, E, N);

    dim3 g1((256 + 63) / 64, (N + 63) / 64);
    k_gemm<<<g1, 256>>>(x, Wl1, (float*)pxl1, N, 256, 128);
    k_gemm<<<g1, 256>>>(x, Wr1, (float*)pxr1, N, 256, 128);

    k_logits1<<<(ET + 7) / 8, 256>>>(ei, att1, E, N);
    k_agg1<<<(N + 7) / 8, 256>>>(b1, N);

    k_bnstats<<<(N + 127) / 128, 256>>>(N);
    k_bnapply<<<(N * 256 + 255) / 256, 256>>>(gamma1, beta1, N);

    dim3 g2((40 + 63) / 64, (N + 63) / 64);
    k_gemm<<<g2, 256>>>((const float*)ph2, Wl2, (float*)pxl2, N, 40, 256);
    k_gemm<<<g2, 256>>>((const float*)ph2, Wr2, (float*)pxr2, N, 40, 256);

    k_logits2<<<(ET + 7) / 8, 256>>>(ei, att2, E, N);
    k_agg2<<<(N + 7) / 8, 256>>>(b2, out, N);
}

// round 3
// speedup vs baseline: 1.3113x; 1.3113x over previous
#include <cuda_runtime.h>
#include <math.h>

#define D1 256
#define C2 40
#define MAXN 50176
#define MAXE 800000
#define MAXET (MAXE + MAXN)

// ---------------- static scratch (no runtime allocation) ----------------
__device__ float g_xl1[(size_t)MAXN * D1];
__device__ float g_xr1[(size_t)MAXN * D1];
__device__ float g_h1 [(size_t)MAXN * D1];
__device__ float g_xl2[(size_t)MAXN * C2];
__device__ float g_xr2[(size_t)MAXN * C2];
__device__ float g_e1 [(size_t)MAXET * 4];
__device__ float g_e2 [MAXET];
__device__ int   g_counts[MAXN + 1];
__device__ int   g_offs  [MAXN + 1];
__device__ int   g_cursor[MAXN + 1];
__device__ int   g_src[MAXET];
__device__ int   g_dst[MAXET];
__device__ float g_bn[512];
__device__ float g_bns[256];
__device__ float g_bnt[256];
__device__ float g_W2[256 * 80];

// ---------------- zero counts + bn accumulators ----------------
__global__ void k_zero(int n) {
    int i = blockIdx.x * blockDim.x + threadIdx.x;
    if (i <= n) g_counts[i] = 0;
    if (i < 512) g_bn[i] = 0.f;
}

// ---------------- CSR build ----------------
__global__ void k_count(const int* __restrict__ ei, int E, int N) {
    int i = blockIdx.x * blockDim.x + threadIdx.x;
    if (i >= E + N) return;
    int dst = (i < E) ? ei[E + i] : (i - E);
    atomicAdd(&g_counts[dst], 1);
}

__global__ void k_scan(int n) {
    __shared__ int sh[1024];
    __shared__ int s_carry;
    int t = threadIdx.x;
    if (t == 0) s_carry = 0;
    __syncthreads();
    for (int base = 0; base < n; base += 1024) {
        int v = (base + t < n) ? g_counts[base + t] : 0;
        sh[t] = v;
        __syncthreads();
        for (int off = 1; off < 1024; off <<= 1) {
            int y = (t >= off) ? sh[t - off] : 0;
            __syncthreads();
            sh[t] += y;
            __syncthreads();
        }
        int out = s_carry + sh[t] - v;   // exclusive
        if (base + t < n) { g_offs[base + t] = out; g_cursor[base + t] = out; }
        __syncthreads();
        if (t == 0) s_carry += sh[1023];
        __syncthreads();
    }
    if (t == 0) g_offs[n] = s_carry;
}

__global__ void k_fill(const int* __restrict__ ei, int E, int N) {
    int i = blockIdx.x * blockDim.x + threadIdx.x;
    if (i >= E + N) return;
    int src, dst;
    if (i < E) { src = ei[i]; dst = ei[E + i]; } else { src = dst = i - E; }
    int p = atomicAdd(&g_cursor[dst], 1);
    g_src[p] = src;
    g_dst[p] = dst;
}

// ---------------- layer-1 SGEMM: C[M,256] = A[M,128] @ B[128,256] ----------------
// 128x128 tile, 256 threads, 8x8 per thread
__global__ __launch_bounds__(256) void k_gemm1(
    const float* __restrict__ A, const float* __restrict__ B,
    float* __restrict__ C, int M)
{
    __shared__ float As[16][132];
    __shared__ float Bs[16][128];
    int tid = threadIdx.x;
    int tx = tid & 15, ty = tid >> 4;
    int m0 = blockIdx.y * 128, n0 = blockIdx.x * 128;
    float acc[8][8] = {};
    for (int k0 = 0; k0 < 128; k0 += 16) {
#pragma unroll
        for (int t = 0; t < 2; t++) {
            int f = tid + t * 256;
            int r = f >> 2, c = (f & 3) * 4;
            int gr = m0 + r;
            float4 v = make_float4(0.f, 0.f, 0.f, 0.f);
            if (gr < M) v = *(const float4*)&A[(size_t)gr * 128 + k0 + c];
            As[c + 0][r] = v.x; As[c + 1][r] = v.y;
            As[c + 2][r] = v.z; As[c + 3][r] = v.w;
        }
#pragma unroll
        for (int t = 0; t < 2; t++) {
            int f = tid + t * 256;
            int r = f >> 5, c = (f & 31) * 4;
            *(float4*)&Bs[r][c] = *(const float4*)&B[(size_t)(k0 + r) * 256 + n0 + c];
        }
        __syncthreads();
#pragma unroll
        for (int kk = 0; kk < 16; kk++) {
            float a[8], b[8];
            *(float4*)(a)     = *(const float4*)&As[kk][ty * 8];
            *(float4*)(a + 4) = *(const float4*)&As[kk][ty * 8 + 4];
            *(float4*)(b)     = *(const float4*)&Bs[kk][tx * 8];
            *(float4*)(b + 4) = *(const float4*)&Bs[kk][tx * 8 + 4];
#pragma unroll
            for (int i = 0; i < 8; i++)
#pragma unroll
                for (int j = 0; j < 8; j++) acc[i][j] += a[i] * b[j];
        }
        __syncthreads();
    }
#pragma unroll
    for (int i = 0; i < 8; i++) {
        int gr = m0 + ty * 8 + i;
        if (gr >= M) continue;
#pragma unroll
        for (int j = 0; j < 8; j += 4) {
            *(float4*)&C[(size_t)gr * 256 + n0 + tx * 8 + j] =
                make_float4(acc[i][j], acc[i][j + 1], acc[i][j + 2], acc[i][j + 3]);
        }
    }
}

// ---------------- layer-1 edge logits (CSR order): warp per slot ----------------
__global__ __launch_bounds__(256) void k_logits1(const float* __restrict__ att, int ET)
{
    int gt = blockIdx.x * blockDim.x + threadIdx.x;
    int p = gt >> 5, lane = gt & 31;
    if (p >= ET) return;
    int src = g_src[p], dst = g_dst[p];
    const float4* pl = (const float4*)g_xl1 + (size_t)src * 64 + lane * 2;
    const float4* pr = (const float4*)g_xr1 + (size_t)dst * 64 + lane * 2;
    const float4* pa = (const float4*)att + lane * 2;
    float s = 0.f;
#pragma unroll
    for (int q = 0; q < 2; q++) {
        float4 a = pl[q], b = pr[q], w4 = pa[q];
        float v;
        v = a.x + b.x; s += fmaxf(v, 0.2f * v) * w4.x;
        v = a.y + b.y; s += fmaxf(v, 0.2f * v) * w4.y;
        v = a.z + b.z; s += fmaxf(v, 0.2f * v) * w4.z;
        v = a.w + b.w; s += fmaxf(v, 0.2f * v) * w4.w;
    }
    s += __shfl_down_sync(0xffffffffu, s, 4, 8);
    s += __shfl_down_sync(0xffffffffu, s, 2, 8);
    s += __shfl_down_sync(0xffffffffu, s, 1, 8);
    if ((lane & 7) == 0) g_e1[(size_t)p * 4 + (lane >> 3)] = s;
}

// ---------------- layer-1 softmax + aggregate: warp per dst node ----------------
__global__ __launch_bounds__(256) void k_agg1(const float* __restrict__ b1, int N)
{
    int gt = blockIdx.x * blockDim.x + threadIdx.x;
    int w = gt >> 5, lane = gt & 31;
    if (w >= N) return;
    int beg = g_offs[w], end = g_offs[w + 1];

    float mx0 = -1e30f, mx1 = -1e30f, mx2 = -1e30f, mx3 = -1e30f;
    for (int p = beg + lane; p < end; p += 32) {
        float4 ev = ((const float4*)g_e1)[p];
        mx0 = fmaxf(mx0, ev.x); mx1 = fmaxf(mx1, ev.y);
        mx2 = fmaxf(mx2, ev.z); mx3 = fmaxf(mx3, ev.w);
    }
#pragma unroll
    for (int off = 16; off; off >>= 1) {
        mx0 = fmaxf(mx0, __shfl_xor_sync(0xffffffffu, mx0, off));
        mx1 = fmaxf(mx1, __shfl_xor_sync(0xffffffffu, mx1, off));
        mx2 = fmaxf(mx2, __shfl_xor_sync(0xffffffffu, mx2, off));
        mx3 = fmaxf(mx3, __shfl_xor_sync(0xffffffffu, mx3, off));
    }
    float dn0 = 0.f, dn1 = 0.f, dn2 = 0.f, dn3 = 0.f;
    for (int p = beg + lane; p < end; p += 32) {
        float4 ev = ((const float4*)g_e1)[p];
        dn0 += expf(ev.x - mx0); dn1 += expf(ev.y - mx1);
        dn2 += expf(ev.z - mx2); dn3 += expf(ev.w - mx3);
    }
#pragma unroll
    for (int off = 16; off; off >>= 1) {
        dn0 += __shfl_xor_sync(0xffffffffu, dn0, off);
        dn1 += __shfl_xor_sync(0xffffffffu, dn1, off);
        dn2 += __shfl_xor_sync(0xffffffffu, dn2, off);
        dn3 += __shfl_xor_sync(0xffffffffu, dn3, off);
    }
    int head = lane >> 3;
    float m  = (lane < 16) ? ((lane < 8) ? mx0 : mx1) : ((lane < 24) ? mx2 : mx3);
    float dd = (lane < 16) ? ((lane < 8) ? dn0 : dn1) : ((lane < 24) ? dn2 : dn3);
    float inv = 1.f / (dd + 1e-16f);

    float acc0 = 0, acc1 = 0, acc2 = 0, acc3 = 0, acc4 = 0, acc5 = 0, acc6 = 0, acc7 = 0;
    for (int p = beg; p < end; p++) {
        int src = g_src[p];
        float ev = g_e1[(size_t)p * 4 + head];
        float al = expf(ev - m) * inv;
        const float4* px = (const float4*)g_xl1 + (size_t)src * 64 + lane * 2;
        float4 a0 = px[0], a1 = px[1];
        acc0 += al * a0.x; acc1 += al * a0.y; acc2 += al * a0.z; acc3 += al * a0.w;
        acc4 += al * a1.x; acc5 += al * a1.y; acc6 += al * a1.z; acc7 += al * a1.w;
    }
    const float4* pb = (const float4*)b1 + lane * 2;
    float4 bb0 = pb[0], bb1 = pb[1];
    float4 o0 = make_float4(acc0 + bb0.x, acc1 + bb0.y, acc2 + bb0.z, acc3 + bb0.w);
    float4 o1 = make_float4(acc4 + bb1.x, acc5 + bb1.y, acc6 + bb1.z, acc7 + bb1.w);
    ((float4*)g_h1)[(size_t)w * 64 + lane * 2 + 0] = o0;
    ((float4*)g_h1)[(size_t)w * 64 + lane * 2 + 1] = o1;
}

// ---------------- batch-norm stats ----------------
__global__ __launch_bounds__(256) void k_bnstats(int N)
{
    int c = threadIdx.x;
    int r0 = blockIdx.x * 128;
    int rend = min(r0 + 128, N);
    float s = 0.f, s2 = 0.f;
    for (int r = r0; r < rend; r++) {
        float v = g_h1[(size_t)r * 256 + c];
        s += v; s2 += v * v;
    }
    atomicAdd(&g_bn[c], s);
    atomicAdd(&g_bn[256 + c], s2);
}

// ---------------- batch-norm finalize: per-channel scale/shift ----------------
__global__ void k_bnfin(const float* __restrict__ gamma,
                        const float* __restrict__ beta, int N)
{
    int c = threadIdx.x;
    float invN = 1.f / (float)N;
    float mu = g_bn[c] * invN;
    float var = g_bn[256 + c] * invN - mu * mu;
    float rs = rsqrtf(var + 1e-5f);
    float s = gamma[c] * rs;
    g_bns[c] = s;
    g_bnt[c] = beta[c] - s * mu;
}

// ---------------- concat W2 = [Wl2 | Wr2] as [256][80] ----------------
__global__ void k_w2cat(const float* __restrict__ Wl2, const float* __restrict__ Wr2)
{
    int i = blockIdx.x * blockDim.x + threadIdx.x;
    if (i >= 256 * 80) return;
    int k = i / 80, c = i % 80;
    g_W2[i] = (c < 40) ? Wl2[k * 40 + c] : Wr2[k * 40 + (c - 40)];
}

// ---------------- layer-2 fused: BN+ELU(A) then GEMM -> xl2|xr2 ----------------
// tile 128 rows x 80 cols, 256 threads, 8x5 per thread
__global__ __launch_bounds__(256) void k_gemm2(float* __restrict__ xl2,
                                               float* __restrict__ xr2, int M)
{
    __shared__ float As[32][132];
    __shared__ float Ws[32][80];
    int tid = threadIdx.x;
    int tx = tid & 15, ty = tid >> 4;
    int m0 = blockIdx.x * 128;
    float acc[8][5] = {};
    for (int k0 = 0; k0 < 256; k0 += 32) {
#pragma unroll
        for (int t = 0; t < 4; t++) {
            int f = tid + t * 256;           // 0..1023
            int r = f >> 3, c = (f & 7) * 4; // 128 rows x 8 float4s
            int gr = m0 + r;
            float4 v = make_float4(0.f, 0.f, 0.f, 0.f);
            if (gr < M) v = *(const float4*)&g_h1[(size_t)gr * 256 + k0 + c];
            float4 s4 = *(const float4*)&g_bns[k0 + c];
            float4 t4 = *(const float4*)&g_bnt[k0 + c];
            float e;
            e = s4.x * v.x + t4.x; As[c + 0][r] = e > 0.f ? e : (expf(e) - 1.f);
            e = s4.y * v.y + t4.y; As[c + 1][r] = e > 0.f ? e : (expf(e) - 1.f);
            e = s4.z * v.z + t4.z; As[c + 2][r] = e > 0.f ? e : (expf(e) - 1.f);
            e = s4.w * v.w + t4.w; As[c + 3][r] = e > 0.f ? e : (expf(e) - 1.f);
        }
#pragma unroll
        for (int t = 0; t < 10; t++) {
            int f = tid + t * 256;           // 0..2559
            int r = f / 80, c = f - r * 80;
            Ws[r][c] = g_W2[(k0 + r) * 80 + c];
        }
        __syncthreads();
#pragma unroll
        for (int kk = 0; kk < 32; kk++) {
            float a[8], b[5];
            *(float4*)(a)     = *(const float4*)&As[kk][ty * 8];
            *(float4*)(a + 4) = *(const float4*)&As[kk][ty * 8 + 4];
#pragma unroll
            for (int j = 0; j < 5; j++) b[j] = Ws[kk][tx * 5 + j];
#pragma unroll
            for (int i = 0; i < 8; i++)
#pragma unroll
                for (int j = 0; j < 5; j++) acc[i][j] += a[i] * b[j];
        }
        __syncthreads();
    }
#pragma unroll
    for (int i = 0; i < 8; i++) {
        int gr = m0 + ty * 8 + i;
        if (gr >= M) continue;
        int c0 = tx * 5;                      // 0..75, never straddles 40
        float* dstp = (c0 < 40) ? &xl2[(size_t)gr * 40 + c0]
                                : &xr2[(size_t)gr * 40 + (c0 - 40)];
#pragma unroll
        for (int j = 0; j < 5; j++) dstp[j] = acc[i][j];
    }
}

// ---------------- layer-2 edge logits (CSR order): warp per slot ----------------
__global__ __launch_bounds__(256) void k_logits2(const float* __restrict__ att2, int ET)
{
    int gt = blockIdx.x * blockDim.x + threadIdx.x;
    int p = gt >> 5, lane = gt & 31;
    if (p >= ET) return;
    int src = g_src[p], dst = g_dst[p];
    float v = g_xl2[(size_t)src * 40 + lane] + g_xr2[(size_t)dst * 40 + lane];
    float s = fmaxf(v, 0.2f * v) * att2[lane];
    if (lane < 8) {
        int c = 32 + lane;
        float v2 = g_xl2[(size_t)src * 40 + c] + g_xr2[(size_t)dst * 40 + c];
        s += fmaxf(v2, 0.2f * v2) * att2[c];
    }
#pragma unroll
    for (int off = 16; off; off >>= 1) s += __shfl_xor_sync(0xffffffffu, s, off);
    if (lane == 0) g_e2[p] = s;
}

// ---------------- layer-2 softmax + aggregate: warp per dst node ----------------
__global__ __launch_bounds__(256) void k_agg2(const float* __restrict__ b2,
                                              float* __restrict__ out, int N)
{
    int gt = blockIdx.x * blockDim.x + threadIdx.x;
    int w = gt >> 5, lane = gt & 31;
    if (w >= N) return;
    int beg = g_offs[w], end = g_offs[w + 1];

    float mx = -1e30f;
    for (int p = beg + lane; p < end; p += 32) mx = fmaxf(mx, g_e2[p]);
#pragma unroll
    for (int off = 16; off; off >>= 1) mx = fmaxf(mx, __shfl_xor_sync(0xffffffffu, mx, off));
    float dn = 0.f;
    for (int p = beg + lane; p < end; p += 32) dn += expf(g_e2[p] - mx);
#pragma unroll
    for (int off = 16; off; off >>= 1) dn += __shfl_xor_sync(0xffffffffu, dn, off);
    float inv = 1.f / (dn + 1e-16f);

    float a0 = 0.f, a1 = 0.f;
    for (int p = beg; p < end; p++) {
        int src = g_src[p];
        float al = expf(g_e2[p] - mx) * inv;
        a0 += al * g_xl2[(size_t)src * 40 + lane];
        if (lane < 8) a1 += al * g_xl2[(size_t)src * 40 + 32 + lane];
    }
    out[(size_t)w * 40 + lane] = a0 + b2[lane];
    if (lane < 8) out[(size_t)w * 40 + 32 + lane] = a1 + b2[32 + lane];
}

// ---------------- host launcher ----------------
extern "C" void kernel_launch(void* const* d_in, const int* in_sizes, int n_in,
                              void* d_out, int out_size)
{
    const float* x      = (const float*)d_in[0];
    const int*   ei     = (const int*)  d_in[1];
    const float* Wl1    = (const float*)d_in[2];
    const float* Wr1    = (const float*)d_in[3];
    const float* att1   = (const float*)d_in[4];
    const float* b1     = (const float*)d_in[5];
    const float* gamma1 = (const float*)d_in[6];
    const float* beta1  = (const float*)d_in[7];
    const float* Wl2    = (const float*)d_in[8];
    const float* Wr2    = (const float*)d_in[9];
    const float* att2   = (const float*)d_in[10];
    const float* b2     = (const float*)d_in[11];
    float* out = (float*)d_out;

    int N = in_sizes[0] / 128;
    int E = in_sizes[1] / 2;
    int ET = E + N;

    void *pxl1, *pxr1, *pxl2, *pxr2;
    cudaGetSymbolAddress(&pxl1, g_xl1);
    cudaGetSymbolAddress(&pxr1, g_xr1);
    cudaGetSymbolAddress(&pxl2, g_xl2);
    cudaGetSymbolAddress(&pxr2, g_xr2);

    k_zero<<<(N + 256) / 256, 256>>>(N);
    k_count<<<(ET + 255) / 256, 256>>>(ei, E, N);
    k_scan<<<1, 1024>>>(N);
    k_fill<<<(ET + 255) / 256, 256>>>(ei, E, N);
    k_w2cat<<<(256 * 80 + 255) / 256, 256>>>(Wl2, Wr2);

    dim3 g1(2, (N + 127) / 128);
    k_gemm1<<<g1, 256>>>(x, Wl1, (float*)pxl1, N);
    k_gemm1<<<g1, 256>>>(x, Wr1, (float*)pxr1, N);

    k_logits1<<<(ET + 7) / 8, 256>>>(att1, ET);
    k_agg1<<<(N + 7) / 8, 256>>>(b1, N);

    k_bnstats<<<(N + 127) / 128, 256>>>(N);
    k_bnfin<<<1, 256>>>(gamma1, beta1, N);

    k_gemm2<<<(N + 127) / 128, 256>>>((float*)pxl2, (float*)pxr2, N);

    k_logits2<<<(ET + 7) / 8, 256>>>(att2, ET);
    k_agg2<<<(N + 7) / 8, 256>>>(b2, out, N);
}

// round 4
// speedup vs baseline: 1.7696x; 1.3495x over previous
#include <cuda_runtime.h>
#include <math.h>
#include <stdint.h>

#define D1 256
#define C2 40
#define MAXN 50176
#define MAXE 800000
#define MAXET (MAXE + MAXN)

// ---------------- static scratch (no runtime allocation) ----------------
__device__ float g_xl1[(size_t)MAXN * D1];
__device__ float g_xr1[(size_t)MAXN * D1];
__device__ float g_h1 [(size_t)MAXN * D1];
__device__ float g_xl2[(size_t)MAXN * C2];
__device__ float g_xr2[(size_t)MAXN * C2];
__device__ float g_e1 [(size_t)MAXET * 4];
__device__ float g_e2 [MAXET];
__device__ int   g_counts[MAXN + 1];
__device__ int   g_offs  [MAXN + 1];
__device__ int   g_cursor[MAXN + 1];
__device__ int   g_src[MAXET];
__device__ int   g_dst[MAXET];
__device__ float g_bn[512];
__device__ float g_bns[256];
__device__ float g_bnt[256];
__device__ float g_W1[128 * 512];   // [Wl1 | Wr1]
__device__ float g_W2[256 * 80];    // [Wl2 | Wr2]

__device__ __forceinline__ uint32_t f2tf32(float f) {
    uint32_t r;
    asm("cvt.rna.tf32.f32 %0, %1;" : "=r"(r) : "f"(f));
    return r;
}

__device__ __forceinline__ void mma_tf32(float c[4], const uint32_t a[4],
                                         uint32_t b0, uint32_t b1) {
    asm volatile(
        "mma.sync.aligned.m16n8k8.row.col.f32.tf32.tf32.f32 "
        "{%0,%1,%2,%3}, {%4,%5,%6,%7}, {%8,%9}, {%0,%1,%2,%3};"
        : "+f"(c[0]), "+f"(c[1]), "+f"(c[2]), "+f"(c[3])
        : "r"(a[0]), "r"(a[1]), "r"(a[2]), "r"(a[3]), "r"(b0), "r"(b1));
}

// ---------------- zero counts + bn accumulators ----------------
__global__ void k_zero(int n) {
    int i = blockIdx.x * blockDim.x + threadIdx.x;
    if (i <= n) g_counts[i] = 0;
    if (i < 512) g_bn[i] = 0.f;
}

// ---------------- CSR build ----------------
__global__ void k_count(const int* __restrict__ ei, int E, int N) {
    int i = blockIdx.x * blockDim.x + threadIdx.x;
    if (i >= E + N) return;
    int dst = (i < E) ? ei[E + i] : (i - E);
    atomicAdd(&g_counts[dst], 1);
}

__global__ void k_scan(int n) {
    __shared__ int wsum[32];
    __shared__ int s_carry;
    int t = threadIdx.x, lane = t & 31, w = t >> 5;
    if (t == 0) s_carry = 0;
    __syncthreads();
    for (int base = 0; base < n; base += 1024) {
        int v = (base + t < n) ? g_counts[base + t] : 0;
        int s = v;
#pragma unroll
        for (int o = 1; o < 32; o <<= 1) {
            int y = __shfl_up_sync(0xffffffffu, s, o);
            if (lane >= o) s += y;
        }
        if (lane == 31) wsum[w] = s;
        __syncthreads();
        if (w == 0) {
            int ws = wsum[lane];
#pragma unroll
            for (int o = 1; o < 32; o <<= 1) {
                int y = __shfl_up_sync(0xffffffffu, ws, o);
                if (lane >= o) ws += y;
            }
            wsum[lane] = ws;
        }
        __syncthreads();
        int excl = s_carry + (w > 0 ? wsum[w - 1] : 0) + s - v;
        if (base + t < n) { g_offs[base + t] = excl; g_cursor[base + t] = excl; }
        int total = wsum[31];
        __syncthreads();
        if (t == 0) s_carry += total;
        __syncthreads();
    }
    if (t == 0) g_offs[n] = s_carry;
}

__global__ void k_fill(const int* __restrict__ ei, int E, int N) {
    int i = blockIdx.x * blockDim.x + threadIdx.x;
    if (i >= E + N) return;
    int src, dst;
    if (i < E) { src = ei[i]; dst = ei[E + i]; } else { src = dst = i - E; }
    int p = atomicAdd(&g_cursor[dst], 1);
    g_src[p] = src;
    g_dst[p] = dst;
}

// ---------------- weight concat ----------------
__global__ void k_w1cat(const float* __restrict__ Wl1, const float* __restrict__ Wr1) {
    int i = blockIdx.x * blockDim.x + threadIdx.x;
    if (i >= 128 * 512) return;
    int k = i >> 9, c = i & 511;
    g_W1[i] = (c < 256) ? Wl1[k * 256 + c] : Wr1[k * 256 + (c - 256)];
}

__global__ void k_w2cat(const float* __restrict__ Wl2, const float* __restrict__ Wr2) {
    int i = blockIdx.x * blockDim.x + threadIdx.x;
    if (i >= 256 * 80) return;
    int k = i / 80, c = i % 80;
    g_W2[i] = (c < 40) ? Wl2[k * 40 + c] : Wr2[k * 40 + (c - 40)];
}

// ---------------- layer-1 tf32 tensor-core GEMM ----------------
// C[M,512] = A[M,128] @ W1[128,512]; output split to xl1 | xr1
// block tile 128x128, 256 thr (8 warps, 4x2), warp tile 32x64
#define SA1 36
#define SB1 136
__global__ __launch_bounds__(256) void k_gemm1_tc(
    const float* __restrict__ A, float* __restrict__ outL,
    float* __restrict__ outR, int M)
{
    __shared__ uint32_t As[128 * SA1];
    __shared__ uint32_t Bs[32 * SB1];
    int tid = threadIdx.x;
    int lane = tid & 31, wid = tid >> 5;
    int warp_m = wid >> 1, warp_n = wid & 1;
    int m0 = blockIdx.y * 128, n0 = blockIdx.x * 128;
    float acc[2][8][4] = {};

    for (int k0 = 0; k0 < 128; k0 += 32) {
#pragma unroll
        for (int i = 0; i < 4; i++) {
            int f = tid + i * 256;
            int r = f >> 3, c4 = (f & 7) * 4;
            int gr = m0 + r;
            float4 v = make_float4(0.f, 0.f, 0.f, 0.f);
            if (gr < M) v = *(const float4*)&A[(size_t)gr * 128 + k0 + c4];
            uint4 u = make_uint4(f2tf32(v.x), f2tf32(v.y), f2tf32(v.z), f2tf32(v.w));
            *(uint4*)&As[r * SA1 + c4] = u;
        }
#pragma unroll
        for (int i = 0; i < 4; i++) {
            int f = tid + i * 256;
            int k = f >> 5, n4 = (f & 31) * 4;
            float4 v = *(const float4*)&g_W1[(size_t)(k0 + k) * 512 + n0 + n4];
            uint4 u = make_uint4(f2tf32(v.x), f2tf32(v.y), f2tf32(v.z), f2tf32(v.w));
            *(uint4*)&Bs[k * SB1 + n4] = u;
        }
        __syncthreads();
#pragma unroll
        for (int ks = 0; ks < 4; ks++) {
            int kk = ks * 8;
            int kc = kk + (lane & 3);
            uint32_t a[2][4];
            int r0 = warp_m * 32 + (lane >> 2);
#pragma unroll
            for (int mi = 0; mi < 2; mi++) {
                int r = r0 + mi * 16;
                a[mi][0] = As[r * SA1 + kc];
                a[mi][1] = As[(r + 8) * SA1 + kc];
                a[mi][2] = As[r * SA1 + kc + 4];
                a[mi][3] = As[(r + 8) * SA1 + kc + 4];
            }
#pragma unroll
            for (int nj = 0; nj < 8; nj++) {
                int n = warp_n * 64 + nj * 8 + (lane >> 2);
                uint32_t b0 = Bs[kc * SB1 + n];
                uint32_t b1 = Bs[(kc + 4) * SB1 + n];
                mma_tf32(acc[0][nj], a[0], b0, b1);
                mma_tf32(acc[1][nj], a[1], b0, b1);
            }
        }
        __syncthreads();
    }

    float* O = (n0 < 256) ? outL : outR;
    int nb = n0 & 255;
#pragma unroll
    for (int mi = 0; mi < 2; mi++) {
        int r = m0 + warp_m * 32 + mi * 16 + (lane >> 2);
#pragma unroll
        for (int nj = 0; nj < 8; nj++) {
            int nc = nb + warp_n * 64 + nj * 8 + (lane & 3) * 2;
            if (r < M)
                *(float2*)&O[(size_t)r * 256 + nc] = make_float2(acc[mi][nj][0], acc[mi][nj][1]);
            if (r + 8 < M)
                *(float2*)&O[(size_t)(r + 8) * 256 + nc] = make_float2(acc[mi][nj][2], acc[mi][nj][3]);
        }
    }
}

// ---------------- layer-1 edge logits (CSR order): warp per slot ----------------
__global__ __launch_bounds__(256) void k_logits1(const float* __restrict__ att, int ET)
{
    int gt = blockIdx.x * blockDim.x + threadIdx.x;
    int p = gt >> 5, lane = gt & 31;
    if (p >= ET) return;
    int src = g_src[p], dst = g_dst[p];
    const float4* pl = (const float4*)g_xl1 + (size_t)src * 64 + lane * 2;
    const float4* pr = (const float4*)g_xr1 + (size_t)dst * 64 + lane * 2;
    const float4* pa = (const float4*)att + lane * 2;
    float s = 0.f;
#pragma unroll
    for (int q = 0; q < 2; q++) {
        float4 a = pl[q], b = pr[q], w4 = pa[q];
        float v;
        v = a.x + b.x; s += fmaxf(v, 0.2f * v) * w4.x;
        v = a.y + b.y; s += fmaxf(v, 0.2f * v) * w4.y;
        v = a.z + b.z; s += fmaxf(v, 0.2f * v) * w4.z;
        v = a.w + b.w; s += fmaxf(v, 0.2f * v) * w4.w;
    }
    s += __shfl_down_sync(0xffffffffu, s, 4, 8);
    s += __shfl_down_sync(0xffffffffu, s, 2, 8);
    s += __shfl_down_sync(0xffffffffu, s, 1, 8);
    if ((lane & 7) == 0) g_e1[(size_t)p * 4 + (lane >> 3)] = s;
}

// ---------------- layer-1 softmax + aggregate: warp per dst node ----------------
__global__ __launch_bounds__(256) void k_agg1(const float* __restrict__ b1, int N)
{
    int gt = blockIdx.x * blockDim.x + threadIdx.x;
    int w = gt >> 5, lane = gt & 31;
    if (w >= N) return;
    int beg = g_offs[w], end = g_offs[w + 1];

    float mx0 = -1e30f, mx1 = -1e30f, mx2 = -1e30f, mx3 = -1e30f;
    for (int p = beg + lane; p < end; p += 32) {
        float4 ev = ((const float4*)g_e1)[p];
        mx0 = fmaxf(mx0, ev.x); mx1 = fmaxf(mx1, ev.y);
        mx2 = fmaxf(mx2, ev.z); mx3 = fmaxf(mx3, ev.w);
    }
#pragma unroll
    for (int off = 16; off; off >>= 1) {
        mx0 = fmaxf(mx0, __shfl_xor_sync(0xffffffffu, mx0, off));
        mx1 = fmaxf(mx1, __shfl_xor_sync(0xffffffffu, mx1, off));
        mx2 = fmaxf(mx2, __shfl_xor_sync(0xffffffffu, mx2, off));
        mx3 = fmaxf(mx3, __shfl_xor_sync(0xffffffffu, mx3, off));
    }
    float dn0 = 0.f, dn1 = 0.f, dn2 = 0.f, dn3 = 0.f;
    for (int p = beg + lane; p < end; p += 32) {
        float4 ev = ((const float4*)g_e1)[p];
        dn0 += expf(ev.x - mx0); dn1 += expf(ev.y - mx1);
        dn2 += expf(ev.z - mx2); dn3 += expf(ev.w - mx3);
    }
#pragma unroll
    for (int off = 16; off; off >>= 1) {
        dn0 += __shfl_xor_sync(0xffffffffu, dn0, off);
        dn1 += __shfl_xor_sync(0xffffffffu, dn1, off);
        dn2 += __shfl_xor_sync(0xffffffffu, dn2, off);
        dn3 += __shfl_xor_sync(0xffffffffu, dn3, off);
    }
    int head = lane >> 3;
    float m  = (lane < 16) ? ((lane < 8) ? mx0 : mx1) : ((lane < 24) ? mx2 : mx3);
    float dd = (lane < 16) ? ((lane < 8) ? dn0 : dn1) : ((lane < 24) ? dn2 : dn3);
    float inv = 1.f / (dd + 1e-16f);

    float acc0 = 0, acc1 = 0, acc2 = 0, acc3 = 0, acc4 = 0, acc5 = 0, acc6 = 0, acc7 = 0;
    for (int p = beg; p < end; p++) {
        int src = g_src[p];
        float ev = g_e1[(size_t)p * 4 + head];
        float al = expf(ev - m) * inv;
        const float4* px = (const float4*)g_xl1 + (size_t)src * 64 + lane * 2;
        float4 a0 = px[0], a1 = px[1];
        acc0 += al * a0.x; acc1 += al * a0.y; acc2 += al * a0.z; acc3 += al * a0.w;
        acc4 += al * a1.x; acc5 += al * a1.y; acc6 += al * a1.z; acc7 += al * a1.w;
    }
    const float4* pb = (const float4*)b1 + lane * 2;
    float4 bb0 = pb[0], bb1 = pb[1];
    float4 o0 = make_float4(acc0 + bb0.x, acc1 + bb0.y, acc2 + bb0.z, acc3 + bb0.w);
    float4 o1 = make_float4(acc4 + bb1.x, acc5 + bb1.y, acc6 + bb1.z, acc7 + bb1.w);
    ((float4*)g_h1)[(size_t)w * 64 + lane * 2 + 0] = o0;
    ((float4*)g_h1)[(size_t)w * 64 + lane * 2 + 1] = o1;
}

// ---------------- batch-norm stats ----------------
__global__ __launch_bounds__(256) void k_bnstats(int N)
{
    int c = threadIdx.x;
    int r0 = blockIdx.x * 128;
    int rend = min(r0 + 128, N);
    float s = 0.f, s2 = 0.f;
    for (int r = r0; r < rend; r++) {
        float v = g_h1[(size_t)r * 256 + c];
        s += v; s2 += v * v;
    }
    atomicAdd(&g_bn[c], s);
    atomicAdd(&g_bn[256 + c], s2);
}

__global__ void k_bnfin(const float* __restrict__ gamma,
                        const float* __restrict__ beta, int N)
{
    int c = threadIdx.x;
    float invN = 1.f / (float)N;
    float mu = g_bn[c] * invN;
    float var = g_bn[256 + c] * invN - mu * mu;
    float rs = rsqrtf(var + 1e-5f);
    float s = gamma[c] * rs;
    g_bns[c] = s;
    g_bnt[c] = beta[c] - s * mu;
}

// ---------------- layer-2 fused BN+ELU + tf32 GEMM ----------------
// C[M,80] = ELU(BN(h1))[M,256] @ W2[256,80]; split to xl2 | xr2
// block tile 128x80, 256 thr (8 warps), warp tile 16x80
#define SA2 36
#define SB2 88
__global__ __launch_bounds__(256) void k_gemm2_tc(float* __restrict__ xl2,
                                                  float* __restrict__ xr2, int M)
{
    __shared__ uint32_t As[128 * SA2];
    __shared__ uint32_t Bs[32 * SB2];
    int tid = threadIdx.x;
    int lane = tid & 31, wid = tid >> 5;
    int m0 = blockIdx.x * 128;
    float acc[10][4] = {};

    for (int k0 = 0; k0 < 256; k0 += 32) {
#pragma unroll
        for (int i = 0; i < 4; i++) {
            int f = tid + i * 256;
            int r = f >> 3, c4 = (f & 7) * 4;
            int gr = m0 + r;
            float4 v = make_float4(0.f, 0.f, 0.f, 0.f);
            if (gr < M) v = *(const float4*)&g_h1[(size_t)gr * 256 + k0 + c4];
            float4 s4 = *(const float4*)&g_bns[k0 + c4];
            float4 t4 = *(const float4*)&g_bnt[k0 + c4];
            float e0 = s4.x * v.x + t4.x; e0 = e0 > 0.f ? e0 : (expf(e0) - 1.f);
            float e1 = s4.y * v.y + t4.y; e1 = e1 > 0.f ? e1 : (expf(e1) - 1.f);
            float e2 = s4.z * v.z + t4.z; e2 = e2 > 0.f ? e2 : (expf(e2) - 1.f);
            float e3 = s4.w * v.w + t4.w; e3 = e3 > 0.f ? e3 : (expf(e3) - 1.f);
            uint4 u = make_uint4(f2tf32(e0), f2tf32(e1), f2tf32(e2), f2tf32(e3));
            *(uint4*)&As[r * SA2 + c4] = u;
        }
        // B: 32 rows x 80 cols = 640 float4
#pragma unroll
        for (int i = 0; i < 3; i++) {
            int f = tid + i * 256;
            if (f < 640) {
                int k = f / 20, n4 = (f % 20) * 4;
                float4 v = *(const float4*)&g_W2[(size_t)(k0 + k) * 80 + n4];
                uint4 u = make_uint4(f2tf32(v.x), f2tf32(v.y), f2tf32(v.z), f2tf32(v.w));
                *(uint4*)&Bs[k * SB2 + n4] = u;
            }
        }
        __syncthreads();
#pragma unroll
        for (int ks = 0; ks < 4; ks++) {
            int kc = ks * 8 + (lane & 3);
            int r = wid * 16 + (lane >> 2);
            uint32_t a[4];
            a[0] = As[r * SA2 + kc];
            a[1] = As[(r + 8) * SA2 + kc];
            a[2] = As[r * SA2 + kc + 4];
            a[3] = As[(r + 8) * SA2 + kc + 4];
#pragma unroll
            for (int nj = 0; nj < 10; nj++) {
                int n = nj * 8 + (lane >> 2);
                uint32_t b0 = Bs[kc * SB2 + n];
                uint32_t b1 = Bs[(kc + 4) * SB2 + n];
                mma_tf32(acc[nj], a, b0, b1);
            }
        }
        __syncthreads();
    }

    int r = m0 + wid * 16 + (lane >> 2);
#pragma unroll
    for (int nj = 0; nj < 10; nj++) {
        int col = nj * 8 + (lane & 3) * 2;
        float* O  = (col < 40) ? xl2 : xr2;
        int cc = col & 127;
        if (col >= 40) cc = col - 40;
        if (r < M)
            *(float2*)&O[(size_t)r * 40 + cc] = make_float2(acc[nj][0], acc[nj][1]);
        if (r + 8 < M)
            *(float2*)&O[(size_t)(r + 8) * 40 + cc] = make_float2(acc[nj][2], acc[nj][3]);
    }
}

// ---------------- layer-2 edge logits (CSR order): warp per slot ----------------
__global__ __launch_bounds__(256) void k_logits2(const float* __restrict__ att2, int ET)
{
    int gt = blockIdx.x * blockDim.x + threadIdx.x;
    int p = gt >> 5, lane = gt & 31;
    if (p >= ET) return;
    int src = g_src[p], dst = g_dst[p];
    float v = g_xl2[(size_t)src * 40 + lane] + g_xr2[(size_t)dst * 40 + lane];
    float s = fmaxf(v, 0.2f * v) * att2[lane];
    if (lane < 8) {
        int c = 32 + lane;
        float v2 = g_xl2[(size_t)src * 40 + c] + g_xr2[(size_t)dst * 40 + c];
        s += fmaxf(v2, 0.2f * v2) * att2[c];
    }
#pragma unroll
    for (int off = 16; off; off >>= 1) s += __shfl_xor_sync(0xffffffffu, s, off);
    if (lane == 0) g_e2[p] = s;
}

// ---------------- layer-2 softmax + aggregate: warp per dst node ----------------
__global__ __launch_bounds__(256) void k_agg2(const float* __restrict__ b2,
                                              float* __restrict__ out, int N)
{
    int gt = blockIdx.x * blockDim.x + threadIdx.x;
    int w = gt >> 5, lane = gt & 31;
    if (w >= N) return;
    int beg = g_offs[w], end = g_offs[w + 1];

    float mx = -1e30f;
    for (int p = beg + lane; p < end; p += 32) mx = fmaxf(mx, g_e2[p]);
#pragma unroll
    for (int off = 16; off; off >>= 1) mx = fmaxf(mx, __shfl_xor_sync(0xffffffffu, mx, off));
    float dn = 0.f;
    for (int p = beg + lane; p < end; p += 32) dn += expf(g_e2[p] - mx);
#pragma unroll
    for (int off = 16; off; off >>= 1) dn += __shfl_xor_sync(0xffffffffu, dn, off);
    float inv = 1.f / (dn + 1e-16f);

    float a0 = 0.f, a1 = 0.f;
    for (int p = beg; p < end; p++) {
        int src = g_src[p];
        float al = expf(g_e2[p] - mx) * inv;
        a0 += al * g_xl2[(size_t)src * 40 + lane];
        if (lane < 8) a1 += al * g_xl2[(size_t)src * 40 + 32 + lane];
    }
    out[(size_t)w * 40 + lane] = a0 + b2[lane];
    if (lane < 8) out[(size_t)w * 40 + 32 + lane] = a1 + b2[32 + lane];
}

// ---------------- host launcher ----------------
extern "C" void kernel_launch(void* const* d_in, const int* in_sizes, int n_in,
                              void* d_out, int out_size)
{
    const float* x      = (const float*)d_in[0];
    const int*   ei     = (const int*)  d_in[1];
    const float* Wl1    = (const float*)d_in[2];
    const float* Wr1    = (const float*)d_in[3];
    const float* att1   = (const float*)d_in[4];
    const float* b1     = (const float*)d_in[5];
    const float* gamma1 = (const float*)d_in[6];
    const float* beta1  = (const float*)d_in[7];
    const float* Wl2    = (const float*)d_in[8];
    const float* Wr2    = (const float*)d_in[9];
    const float* att2   = (const float*)d_in[10];
    const float* b2     = (const float*)d_in[11];
    float* out = (float*)d_out;

    int N = in_sizes[0] / 128;
    int E = in_sizes[1] / 2;
    int ET = E + N;

    void *pxl1, *pxr1, *pxl2, *pxr2;
    cudaGetSymbolAddress(&pxl1, g_xl1);
    cudaGetSymbolAddress(&pxr1, g_xr1);
    cudaGetSymbolAddress(&pxl2, g_xl2);
    cudaGetSymbolAddress(&pxr2, g_xr2);

    k_zero<<<(N + 256) / 256, 256>>>(N);
    k_count<<<(ET + 255) / 256, 256>>>(ei, E, N);
    k_scan<<<1, 1024>>>(N);
    k_fill<<<(ET + 255) / 256, 256>>>(ei, E, N);
    k_w1cat<<<(128 * 512 + 255) / 256, 256>>>(Wl1, Wr1);
    k_w2cat<<<(256 * 80 + 255) / 256, 256>>>(Wl2, Wr2);

    dim3 g1(4, (N + 127) / 128);
    k_gemm1_tc<<<g1, 256>>>(x, (float*)pxl1, (float*)pxr1, N);

    k_logits1<<<(ET + 7) / 8, 256>>>(att1, ET);
    k_agg1<<<(N + 7) / 8, 256>>>(b1, N);

    k_bnstats<<<(N + 127) / 128, 256>>>(N);
    k_bnfin<<<1, 256>>>(gamma1, beta1, N);

    k_gemm2_tc<<<(N + 127) / 128, 256>>>((float*)pxl2, (float*)pxr2, N);

    k_logits2<<<(ET + 7) / 8, 256>>>(att2, ET);
    k_agg2<<<(N + 7) / 8, 256>>>(b2, out, N);
}

// round 5
// speedup vs baseline: 2.5157x; 1.4216x over previous
#include <cuda_runtime.h>
#include <math.h>
#include <stdint.h>

#define D1 256
#define C2 40
#define MAXN 50176
#define MAXE 800000
#define MAXET (MAXE + MAXN)

// ---------------- static scratch (no runtime allocation) ----------------
__device__ float g_xl1[(size_t)MAXN * D1];
__device__ float g_xr1[(size_t)MAXN * D1];
__device__ float g_h1 [(size_t)MAXN * D1];
__device__ float g_xl2[(size_t)MAXN * C2];
__device__ float g_xr2[(size_t)MAXN * C2];
__device__ float g_e1 [(size_t)MAXET * 4];
__device__ float g_e2 [MAXET];
__device__ int   g_counts[MAXN + 1];
__device__ int   g_offs  [MAXN + 1];
__device__ int   g_cursor[MAXN + 1];
__device__ int   g_src[MAXET];
__device__ float g_bn[512];
__device__ float g_bns[256];
__device__ float g_bnt[256];
__device__ float g_W1[128 * 512];   // [Wl1 | Wr1]
__device__ float g_W2[256 * 80];    // [Wl2 | Wr2]

__device__ __forceinline__ uint32_t f2tf32(float f) {
    uint32_t r;
    asm("cvt.rna.tf32.f32 %0, %1;" : "=r"(r) : "f"(f));
    return r;
}

__device__ __forceinline__ void mma_tf32(float c[4], const uint32_t a[4],
                                         uint32_t b0, uint32_t b1) {
    asm volatile(
        "mma.sync.aligned.m16n8k8.row.col.f32.tf32.tf32.f32 "
        "{%0,%1,%2,%3}, {%4,%5,%6,%7}, {%8,%9}, {%0,%1,%2,%3};"
        : "+f"(c[0]), "+f"(c[1]), "+f"(c[2]), "+f"(c[3])
        : "r"(a[0]), "r"(a[1]), "r"(a[2]), "r"(a[3]), "r"(b0), "r"(b1));
}

// ---------------- zero counts + bn accumulators ----------------
__global__ void k_zero(int n) {
    int i = blockIdx.x * blockDim.x + threadIdx.x;
    if (i <= n) g_counts[i] = 0;
    if (i < 512) g_bn[i] = 0.f;
}

// ---------------- CSR build ----------------
__global__ void k_count(const int* __restrict__ ei, int E, int N) {
    int i = blockIdx.x * blockDim.x + threadIdx.x;
    if (i >= E + N) return;
    int dst = (i < E) ? ei[E + i] : (i - E);
    atomicAdd(&g_counts[dst], 1);
}

__global__ void k_scan(int n) {
    __shared__ int wsum[32];
    __shared__ int s_carry;
    int t = threadIdx.x, lane = t & 31, w = t >> 5;
    if (t == 0) s_carry = 0;
    __syncthreads();
    for (int base = 0; base < n; base += 1024) {
        int v = (base + t < n) ? g_counts[base + t] : 0;
        int s = v;
#pragma unroll
        for (int o = 1; o < 32; o <<= 1) {
            int y = __shfl_up_sync(0xffffffffu, s, o);
            if (lane >= o) s += y;
        }
        if (lane == 31) wsum[w] = s;
        __syncthreads();
        if (w == 0) {
            int ws = wsum[lane];
#pragma unroll
            for (int o = 1; o < 32; o <<= 1) {
                int y = __shfl_up_sync(0xffffffffu, ws, o);
                if (lane >= o) ws += y;
            }
            wsum[lane] = ws;
        }
        __syncthreads();
        int excl = s_carry + (w > 0 ? wsum[w - 1] : 0) + s - v;
        if (base + t < n) { g_offs[base + t] = excl; g_cursor[base + t] = excl; }
        int total = wsum[31];
        __syncthreads();
        if (t == 0) s_carry += total;
        __syncthreads();
    }
    if (t == 0) g_offs[n] = s_carry;
}

__global__ void k_fill(const int* __restrict__ ei, int E, int N) {
    int i = blockIdx.x * blockDim.x + threadIdx.x;
    if (i >= E + N) return;
    int src, dst;
    if (i < E) { src = ei[i]; dst = ei[E + i]; } else { src = dst = i - E; }
    int p = atomicAdd(&g_cursor[dst], 1);
    g_src[p] = src;
}

// ---------------- weight concat ----------------
__global__ void k_w1cat(const float* __restrict__ Wl1, const float* __restrict__ Wr1) {
    int i = blockIdx.x * blockDim.x + threadIdx.x;
    if (i >= 128 * 512) return;
    int k = i >> 9, c = i & 511;
    g_W1[i] = (c < 256) ? Wl1[k * 256 + c] : Wr1[k * 256 + (c - 256)];
}

__global__ void k_w2cat(const float* __restrict__ Wl2, const float* __restrict__ Wr2) {
    int i = blockIdx.x * blockDim.x + threadIdx.x;
    if (i >= 256 * 80) return;
    int k = i / 80, c = i % 80;
    g_W2[i] = (c < 40) ? Wl2[k * 40 + c] : Wr2[k * 40 + (c - 40)];
}

// ---------------- layer-1 tf32 tensor-core GEMM ----------------
#define SA1 36
#define SB1 136
__global__ __launch_bounds__(256) void k_gemm1_tc(
    const float* __restrict__ A, float* __restrict__ outL,
    float* __restrict__ outR, int M)
{
    __shared__ uint32_t As[128 * SA1];
    __shared__ uint32_t Bs[32 * SB1];
    int tid = threadIdx.x;
    int lane = tid & 31, wid = tid >> 5;
    int warp_m = wid >> 1, warp_n = wid & 1;
    int m0 = blockIdx.y * 128, n0 = blockIdx.x * 128;
    float acc[2][8][4] = {};

    for (int k0 = 0; k0 < 128; k0 += 32) {
#pragma unroll
        for (int i = 0; i < 4; i++) {
            int f = tid + i * 256;
            int r = f >> 3, c4 = (f & 7) * 4;
            int gr = m0 + r;
            float4 v = make_float4(0.f, 0.f, 0.f, 0.f);
            if (gr < M) v = *(const float4*)&A[(size_t)gr * 128 + k0 + c4];
            uint4 u = make_uint4(f2tf32(v.x), f2tf32(v.y), f2tf32(v.z), f2tf32(v.w));
            *(uint4*)&As[r * SA1 + c4] = u;
        }
#pragma unroll
        for (int i = 0; i < 4; i++) {
            int f = tid + i * 256;
            int k = f >> 5, n4 = (f & 31) * 4;
            float4 v = *(const float4*)&g_W1[(size_t)(k0 + k) * 512 + n0 + n4];
            uint4 u = make_uint4(f2tf32(v.x), f2tf32(v.y), f2tf32(v.z), f2tf32(v.w));
            *(uint4*)&Bs[k * SB1 + n4] = u;
        }
        __syncthreads();
#pragma unroll
        for (int ks = 0; ks < 4; ks++) {
            int kc = ks * 8 + (lane & 3);
            uint32_t a[2][4];
            int r0 = warp_m * 32 + (lane >> 2);
#pragma unroll
            for (int mi = 0; mi < 2; mi++) {
                int r = r0 + mi * 16;
                a[mi][0] = As[r * SA1 + kc];
                a[mi][1] = As[(r + 8) * SA1 + kc];
                a[mi][2] = As[r * SA1 + kc + 4];
                a[mi][3] = As[(r + 8) * SA1 + kc + 4];
            }
#pragma unroll
            for (int nj = 0; nj < 8; nj++) {
                int n = warp_n * 64 + nj * 8 + (lane >> 2);
                uint32_t b0 = Bs[kc * SB1 + n];
                uint32_t b1 = Bs[(kc + 4) * SB1 + n];
                mma_tf32(acc[0][nj], a[0], b0, b1);
                mma_tf32(acc[1][nj], a[1], b0, b1);
            }
        }
        __syncthreads();
    }

    float* O = (n0 < 256) ? outL : outR;
    int nb = n0 & 255;
#pragma unroll
    for (int mi = 0; mi < 2; mi++) {
        int r = m0 + warp_m * 32 + mi * 16 + (lane >> 2);
#pragma unroll
        for (int nj = 0; nj < 8; nj++) {
            int nc = nb + warp_n * 64 + nj * 8 + (lane & 3) * 2;
            if (r < M)
                *(float2*)&O[(size_t)r * 256 + nc] = make_float2(acc[mi][nj][0], acc[mi][nj][1]);
            if (r + 8 < M)
                *(float2*)&O[(size_t)(r + 8) * 256 + nc] = make_float2(acc[mi][nj][2], acc[mi][nj][3]);
        }
    }
}

// ---------------- layer-1 fused logits+softmax+aggregate: warp per dst ----------------
__global__ __launch_bounds__(256) void k_attn1(const float* __restrict__ att,
                                               const float* __restrict__ b1, int N)
{
    int gt = blockIdx.x * blockDim.x + threadIdx.x;
    int w = gt >> 5, lane = gt & 31;
    if (w >= N) return;
    int beg = g_offs[w], end = g_offs[w + 1];

    // preload xr row + att for this lane's 8 channels (all in head lane>>3)
    const float4* pxr = (const float4*)g_xr1 + (size_t)w * 64 + lane * 2;
    float4 r0 = pxr[0], r1 = pxr[1];
    const float4* pa = (const float4*)att + lane * 2;
    float4 at0 = pa[0], at1 = pa[1];

    // pass A: per-edge logits (warp-wide), track per-head running max
    float mx = -1e30f;
    for (int p = beg; p < end; p++) {
        int src = g_src[p];
        const float4* pl = (const float4*)g_xl1 + (size_t)src * 64 + lane * 2;
        float4 a0 = pl[0], a1 = pl[1];
        float v, s = 0.f;
        v = a0.x + r0.x; s += fmaxf(v, 0.2f * v) * at0.x;
        v = a0.y + r0.y; s += fmaxf(v, 0.2f * v) * at0.y;
        v = a0.z + r0.z; s += fmaxf(v, 0.2f * v) * at0.z;
        v = a0.w + r0.w; s += fmaxf(v, 0.2f * v) * at0.w;
        v = a1.x + r1.x; s += fmaxf(v, 0.2f * v) * at1.x;
        v = a1.y + r1.y; s += fmaxf(v, 0.2f * v) * at1.y;
        v = a1.z + r1.z; s += fmaxf(v, 0.2f * v) * at1.z;
        v = a1.w + r1.w; s += fmaxf(v, 0.2f * v) * at1.w;
        s += __shfl_xor_sync(0xffffffffu, s, 4);
        s += __shfl_xor_sync(0xffffffffu, s, 2);
        s += __shfl_xor_sync(0xffffffffu, s, 1);
        mx = fmaxf(mx, s);
        if ((lane & 7) == 0) g_e1[(size_t)p * 4 + (lane >> 3)] = s;
    }
    __threadfence_block();
    __syncwarp();

    // broadcast per-head maxima
    float mh0 = __shfl_sync(0xffffffffu, mx, 0);
    float mh1 = __shfl_sync(0xffffffffu, mx, 8);
    float mh2 = __shfl_sync(0xffffffffu, mx, 16);
    float mh3 = __shfl_sync(0xffffffffu, mx, 24);

    // pass B: denominators
    float dn0 = 0.f, dn1 = 0.f, dn2 = 0.f, dn3 = 0.f;
    for (int p = beg + lane; p < end; p += 32) {
        float4 ev = ((const float4*)g_e1)[p];
        dn0 += expf(ev.x - mh0); dn1 += expf(ev.y - mh1);
        dn2 += expf(ev.z - mh2); dn3 += expf(ev.w - mh3);
    }
#pragma unroll
    for (int off = 16; off; off >>= 1) {
        dn0 += __shfl_xor_sync(0xffffffffu, dn0, off);
        dn1 += __shfl_xor_sync(0xffffffffu, dn1, off);
        dn2 += __shfl_xor_sync(0xffffffffu, dn2, off);
        dn3 += __shfl_xor_sync(0xffffffffu, dn3, off);
    }
    int head = lane >> 3;
    float m  = (head == 0) ? mh0 : (head == 1) ? mh1 : (head == 2) ? mh2 : mh3;
    float dd = (head == 0) ? dn0 : (head == 1) ? dn1 : (head == 2) ? dn2 : dn3;
    float inv = 1.f / (dd + 1e-16f);

    // pass C: aggregate
    float acc0 = 0, acc1 = 0, acc2 = 0, acc3 = 0, acc4 = 0, acc5 = 0, acc6 = 0, acc7 = 0;
    for (int p = beg; p < end; p++) {
        int src = g_src[p];
        float ev = g_e1[(size_t)p * 4 + head];
        float al = expf(ev - m) * inv;
        const float4* px = (const float4*)g_xl1 + (size_t)src * 64 + lane * 2;
        float4 a0 = px[0], a1 = px[1];
        acc0 += al * a0.x; acc1 += al * a0.y; acc2 += al * a0.z; acc3 += al * a0.w;
        acc4 += al * a1.x; acc5 += al * a1.y; acc6 += al * a1.z; acc7 += al * a1.w;
    }
    const float4* pb = (const float4*)b1 + lane * 2;
    float4 bb0 = pb[0], bb1 = pb[1];
    ((float4*)g_h1)[(size_t)w * 64 + lane * 2 + 0] =
        make_float4(acc0 + bb0.x, acc1 + bb0.y, acc2 + bb0.z, acc3 + bb0.w);
    ((float4*)g_h1)[(size_t)w * 64 + lane * 2 + 1] =
        make_float4(acc4 + bb1.x, acc5 + bb1.y, acc6 + bb1.z, acc7 + bb1.w);
}

// ---------------- batch-norm stats ----------------
__global__ __launch_bounds__(256) void k_bnstats(int N)
{
    int c = threadIdx.x;
    int r0 = blockIdx.x * 128;
    int rend = min(r0 + 128, N);
    float s = 0.f, s2 = 0.f;
    for (int r = r0; r < rend; r++) {
        float v = g_h1[(size_t)r * 256 + c];
        s += v; s2 += v * v;
    }
    atomicAdd(&g_bn[c], s);
    atomicAdd(&g_bn[256 + c], s2);
}

__global__ void k_bnfin(const float* __restrict__ gamma,
                        const float* __restrict__ beta, int N)
{
    int c = threadIdx.x;
    float invN = 1.f / (float)N;
    float mu = g_bn[c] * invN;
    float var = g_bn[256 + c] * invN - mu * mu;
    float rs = rsqrtf(var + 1e-5f);
    float s = gamma[c] * rs;
    g_bns[c] = s;
    g_bnt[c] = beta[c] - s * mu;
}

// ---------------- layer-2 fused BN+ELU + tf32 GEMM ----------------
#define SA2 36
#define SB2 88
__global__ __launch_bounds__(256) void k_gemm2_tc(float* __restrict__ xl2,
                                                  float* __restrict__ xr2, int M)
{
    __shared__ uint32_t As[128 * SA2];
    __shared__ uint32_t Bs[32 * SB2];
    int tid = threadIdx.x;
    int lane = tid & 31, wid = tid >> 5;
    int m0 = blockIdx.x * 128;
    float acc[10][4] = {};

    for (int k0 = 0; k0 < 256; k0 += 32) {
#pragma unroll
        for (int i = 0; i < 4; i++) {
            int f = tid + i * 256;
            int r = f >> 3, c4 = (f & 7) * 4;
            int gr = m0 + r;
            float4 v = make_float4(0.f, 0.f, 0.f, 0.f);
            if (gr < M) v = *(const float4*)&g_h1[(size_t)gr * 256 + k0 + c4];
            float4 s4 = *(const float4*)&g_bns[k0 + c4];
            float4 t4 = *(const float4*)&g_bnt[k0 + c4];
            float e0 = s4.x * v.x + t4.x; e0 = e0 > 0.f ? e0 : (expf(e0) - 1.f);
            float e1 = s4.y * v.y + t4.y; e1 = e1 > 0.f ? e1 : (expf(e1) - 1.f);
            float e2 = s4.z * v.z + t4.z; e2 = e2 > 0.f ? e2 : (expf(e2) - 1.f);
            float e3 = s4.w * v.w + t4.w; e3 = e3 > 0.f ? e3 : (expf(e3) - 1.f);
            uint4 u = make_uint4(f2tf32(e0), f2tf32(e1), f2tf32(e2), f2tf32(e3));
            *(uint4*)&As[r * SA2 + c4] = u;
        }
#pragma unroll
        for (int i = 0; i < 3; i++) {
            int f = tid + i * 256;
            if (f < 640) {
                int k = f / 20, n4 = (f % 20) * 4;
                float4 v = *(const float4*)&g_W2[(size_t)(k0 + k) * 80 + n4];
                uint4 u = make_uint4(f2tf32(v.x), f2tf32(v.y), f2tf32(v.z), f2tf32(v.w));
                *(uint4*)&Bs[k * SB2 + n4] = u;
            }
        }
        __syncthreads();
#pragma unroll
        for (int ks = 0; ks < 4; ks++) {
            int kc = ks * 8 + (lane & 3);
            int r = wid * 16 + (lane >> 2);
            uint32_t a[4];
            a[0] = As[r * SA2 + kc];
            a[1] = As[(r + 8) * SA2 + kc];
            a[2] = As[r * SA2 + kc + 4];
            a[3] = As[(r + 8) * SA2 + kc + 4];
#pragma unroll
            for (int nj = 0; nj < 10; nj++) {
                int n = nj * 8 + (lane >> 2);
                uint32_t b0 = Bs[kc * SB2 + n];
                uint32_t b1 = Bs[(kc + 4) * SB2 + n];
                mma_tf32(acc[nj], a, b0, b1);
            }
        }
        __syncthreads();
    }

    int r = m0 + wid * 16 + (lane >> 2);
#pragma unroll
    for (int nj = 0; nj < 10; nj++) {
        int col = nj * 8 + (lane & 3) * 2;
        float* O  = (col < 40) ? xl2 : xr2;
        int cc = (col < 40) ? col : col - 40;
        if (r < M)
            *(float2*)&O[(size_t)r * 40 + cc] = make_float2(acc[nj][0], acc[nj][1]);
        if (r + 8 < M)
            *(float2*)&O[(size_t)(r + 8) * 40 + cc] = make_float2(acc[nj][2], acc[nj][3]);
    }
}

// ---------------- layer-2 fused logits+softmax+aggregate: warp per dst ----------------
__global__ __launch_bounds__(256) void k_attn2(const float* __restrict__ att2,
                                               const float* __restrict__ b2,
                                               float* __restrict__ out, int N)
{
    int gt = blockIdx.x * blockDim.x + threadIdx.x;
    int w = gt >> 5, lane = gt & 31;
    if (w >= N) return;
    int beg = g_offs[w], end = g_offs[w + 1];
    int sub = lane >> 3, l8 = lane & 7;

    // pass A layout: 8-lane group per edge, lane covers channels l8*5 .. l8*5+4
    float xr[5], at[5];
#pragma unroll
    for (int j = 0; j < 5; j++) {
        int c = l8 * 5 + j;
        xr[j] = g_xr2[(size_t)w * 40 + c];
        at[j] = att2[c];
    }

    float mx = -1e30f;
    for (int p0 = beg; p0 < end; p0 += 4) {
        int p = p0 + sub;
        bool valid = (p < end);
        int src = g_src[valid ? p : beg];
        float s = 0.f;
#pragma unroll
        for (int j = 0; j < 5; j++) {
            float v = g_xl2[(size_t)src * 40 + l8 * 5 + j] + xr[j];
            s += fmaxf(v, 0.2f * v) * at[j];
        }
        s += __shfl_xor_sync(0xffffffffu, s, 4);
        s += __shfl_xor_sync(0xffffffffu, s, 2);
        s += __shfl_xor_sync(0xffffffffu, s, 1);
        if (valid) {
            mx = fmaxf(mx, s);
            if (l8 == 0) g_e2[p] = s;
        }
    }
    mx = fmaxf(mx, __shfl_xor_sync(0xffffffffu, mx, 8));
    mx = fmaxf(mx, __shfl_xor_sync(0xffffffffu, mx, 16));
    __threadfence_block();
    __syncwarp();

    float dn = 0.f;
    for (int p = beg + lane; p < end; p += 32) dn += expf(g_e2[p] - mx);
#pragma unroll
    for (int off = 16; off; off >>= 1) dn += __shfl_xor_sync(0xffffffffu, dn, off);
    float inv = 1.f / (dn + 1e-16f);

    float a0 = 0.f, a1 = 0.f;
    for (int p = beg; p < end; p++) {
        int src = g_src[p];
        float al = expf(g_e2[p] - mx) * inv;
        a0 += al * g_xl2[(size_t)src * 40 + lane];
        if (lane < 8) a1 += al * g_xl2[(size_t)src * 40 + 32 + lane];
    }
    out[(size_t)w * 40 + lane] = a0 + b2[lane];
    if (lane < 8) out[(size_t)w * 40 + 32 + lane] = a1 + b2[32 + lane];
}

// ---------------- host launcher ----------------
extern "C" void kernel_launch(void* const* d_in, const int* in_sizes, int n_in,
                              void* d_out, int out_size)
{
    const float* x      = (const float*)d_in[0];
    const int*   ei     = (const int*)  d_in[1];
    const float* Wl1    = (const float*)d_in[2];
    const float* Wr1    = (const float*)d_in[3];
    const float* att1   = (const float*)d_in[4];
    const float* b1     = (const float*)d_in[5];
    const float* gamma1 = (const float*)d_in[6];
    const float* beta1  = (const float*)d_in[7];
    const float* Wl2    = (const float*)d_in[8];
    const float* Wr2    = (const float*)d_in[9];
    const float* att2   = (const float*)d_in[10];
    const float* b2     = (const float*)d_in[11];
    float* out = (float*)d_out;

    int N = in_sizes[0] / 128;
    int E = in_sizes[1] / 2;
    int ET = E + N;

    void *pxl1, *pxr1, *pxl2, *pxr2;
    cudaGetSymbolAddress(&pxl1, g_xl1);
    cudaGetSymbolAddress(&pxr1, g_xr1);
    cudaGetSymbolAddress(&pxl2, g_xl2);
    cudaGetSymbolAddress(&pxr2, g_xr2);

    k_zero<<<(N + 256) / 256, 256>>>(N);
    k_count<<<(ET + 255) / 256, 256>>>(ei, E, N);
    k_scan<<<1, 1024>>>(N);
    k_fill<<<(ET + 255) / 256, 256>>>(ei, E, N);
    k_w1cat<<<(128 * 512 + 255) / 256, 256>>>(Wl1, Wr1);
    k_w2cat<<<(256 * 80 + 255) / 256, 256>>>(Wl2, Wr2);

    dim3 g1(4, (N + 127) / 128);
    k_gemm1_tc<<<g1, 256>>>(x, (float*)pxl1, (float*)pxr1, N);

    k_attn1<<<(N + 7) / 8, 256>>>(att1, b1, N);

    k_bnstats<<<(N + 127) / 128, 256>>>(N);
    k_bnfin<<<1, 256>>>(gamma1, beta1, N);

    k_gemm2_tc<<<(N + 127) / 128, 256>>>((float*)pxl2, (float*)pxr2, N);

    k_attn2<<<(N + 7) / 8, 256>>>(att2, b2, out, N);
}

// round 6
// speedup vs baseline: 2.9449x; 1.1706x over previous
#include <cuda_runtime.h>
#include <math.h>
#include <stdint.h>

#define D1 256
#define C2 40
#define MAXN 50176
#define MAXE 800000
#define MAXET (MAXE + MAXN)

// ---------------- static scratch (no runtime allocation) ----------------
__device__ float g_xl1[(size_t)MAXN * D1];
__device__ float g_xr1[(size_t)MAXN * D1];
__device__ float g_h1 [(size_t)MAXN * D1];
__device__ float g_xl2[(size_t)MAXN * C2];
__device__ float g_xr2[(size_t)MAXN * C2];
__device__ int   g_counts[MAXN + 1];
__device__ int   g_offs  [MAXN + 1];
__device__ int   g_cursor[MAXN + 1];
__device__ int   g_src[MAXET];
__device__ float g_bn[512];
__device__ float g_bns[256];
__device__ float g_bnt[256];
__device__ float g_W1[128 * 512];   // [Wl1 | Wr1]
__device__ float g_W2[256 * 80];    // [Wl2 | Wr2]

__device__ __forceinline__ uint32_t f2tf32(float f) {
    uint32_t r;
    asm("cvt.rna.tf32.f32 %0, %1;" : "=r"(r) : "f"(f));
    return r;
}

__device__ __forceinline__ void mma_tf32(float c[4], const uint32_t a[4],
                                         uint32_t b0, uint32_t b1) {
    asm volatile(
        "mma.sync.aligned.m16n8k8.row.col.f32.tf32.tf32.f32 "
        "{%0,%1,%2,%3}, {%4,%5,%6,%7}, {%8,%9}, {%0,%1,%2,%3};"
        : "+f"(c[0]), "+f"(c[1]), "+f"(c[2]), "+f"(c[3])
        : "r"(a[0]), "r"(a[1]), "r"(a[2]), "r"(a[3]), "r"(b0), "r"(b1));
}

// ---------------- zero counts + bn accumulators ----------------
__global__ void k_zero(int n) {
    int i = blockIdx.x * blockDim.x + threadIdx.x;
    if (i <= n) g_counts[i] = 0;
    if (i < 512) g_bn[i] = 0.f;
}

// ---------------- CSR build ----------------
__global__ void k_count(const int* __restrict__ ei, int E, int N) {
    int i = blockIdx.x * blockDim.x + threadIdx.x;
    if (i >= E + N) return;
    int dst = (i < E) ? ei[E + i] : (i - E);
    atomicAdd(&g_counts[dst], 1);
}

__global__ void k_scan(int n) {
    __shared__ int wsum[32];
    __shared__ int s_carry;
    int t = threadIdx.x, lane = t & 31, w = t >> 5;
    if (t == 0) s_carry = 0;
    __syncthreads();
    for (int base = 0; base < n; base += 1024) {
        int v = (base + t < n) ? g_counts[base + t] : 0;
        int s = v;
#pragma unroll
        for (int o = 1; o < 32; o <<= 1) {
            int y = __shfl_up_sync(0xffffffffu, s, o);
            if (lane >= o) s += y;
        }
        if (lane == 31) wsum[w] = s;
        __syncthreads();
        if (w == 0) {
            int ws = wsum[lane];
#pragma unroll
            for (int o = 1; o < 32; o <<= 1) {
                int y = __shfl_up_sync(0xffffffffu, ws, o);
                if (lane >= o) ws += y;
            }
            wsum[lane] = ws;
        }
        __syncthreads();
        int excl = s_carry + (w > 0 ? wsum[w - 1] : 0) + s - v;
        if (base + t < n) { g_offs[base + t] = excl; g_cursor[base + t] = excl; }
        int total = wsum[31];
        __syncthreads();
        if (t == 0) s_carry += total;
        __syncthreads();
    }
    if (t == 0) g_offs[n] = s_carry;
}

__global__ void k_fill(const int* __restrict__ ei, int E, int N) {
    int i = blockIdx.x * blockDim.x + threadIdx.x;
    if (i >= E + N) return;
    int src, dst;
    if (i < E) { src = ei[i]; dst = ei[E + i]; } else { src = dst = i - E; }
    int p = atomicAdd(&g_cursor[dst], 1);
    g_src[p] = src;
}

// ---------------- weight concat ----------------
__global__ void k_w1cat(const float* __restrict__ Wl1, const float* __restrict__ Wr1) {
    int i = blockIdx.x * blockDim.x + threadIdx.x;
    if (i >= 128 * 512) return;
    int k = i >> 9, c = i & 511;
    g_W1[i] = (c < 256) ? Wl1[k * 256 + c] : Wr1[k * 256 + (c - 256)];
}

__global__ void k_w2cat(const float* __restrict__ Wl2, const float* __restrict__ Wr2) {
    int i = blockIdx.x * blockDim.x + threadIdx.x;
    if (i >= 256 * 80) return;
    int k = i / 80, c = i % 80;
    g_W2[i] = (c < 40) ? Wl2[k * 40 + c] : Wr2[k * 40 + (c - 40)];
}

// ---------------- layer-1 tf32 tensor-core GEMM ----------------
#define SA1 36
#define SB1 136
__global__ __launch_bounds__(256) void k_gemm1_tc(
    const float* __restrict__ A, float* __restrict__ outL,
    float* __restrict__ outR, int M)
{
    __shared__ uint32_t As[128 * SA1];
    __shared__ uint32_t Bs[32 * SB1];
    int tid = threadIdx.x;
    int lane = tid & 31, wid = tid >> 5;
    int warp_m = wid >> 1, warp_n = wid & 1;
    int m0 = blockIdx.y * 128, n0 = blockIdx.x * 128;
    float acc[2][8][4] = {};

    for (int k0 = 0; k0 < 128; k0 += 32) {
#pragma unroll
        for (int i = 0; i < 4; i++) {
            int f = tid + i * 256;
            int r = f >> 3, c4 = (f & 7) * 4;
            int gr = m0 + r;
            float4 v = make_float4(0.f, 0.f, 0.f, 0.f);
            if (gr < M) v = *(const float4*)&A[(size_t)gr * 128 + k0 + c4];
            uint4 u = make_uint4(f2tf32(v.x), f2tf32(v.y), f2tf32(v.z), f2tf32(v.w));
            *(uint4*)&As[r * SA1 + c4] = u;
        }
#pragma unroll
        for (int i = 0; i < 4; i++) {
            int f = tid + i * 256;
            int k = f >> 5, n4 = (f & 31) * 4;
            float4 v = *(const float4*)&g_W1[(size_t)(k0 + k) * 512 + n0 + n4];
            uint4 u = make_uint4(f2tf32(v.x), f2tf32(v.y), f2tf32(v.z), f2tf32(v.w));
            *(uint4*)&Bs[k * SB1 + n4] = u;
        }
        __syncthreads();
#pragma unroll
        for (int ks = 0; ks < 4; ks++) {
            int kc = ks * 8 + (lane & 3);
            uint32_t a[2][4];
            int r0 = warp_m * 32 + (lane >> 2);
#pragma unroll
            for (int mi = 0; mi < 2; mi++) {
                int r = r0 + mi * 16;
                a[mi][0] = As[r * SA1 + kc];
                a[mi][1] = As[(r + 8) * SA1 + kc];
                a[mi][2] = As[r * SA1 + kc + 4];
                a[mi][3] = As[(r + 8) * SA1 + kc + 4];
            }
#pragma unroll
            for (int nj = 0; nj < 8; nj++) {
                int n = warp_n * 64 + nj * 8 + (lane >> 2);
                uint32_t b0 = Bs[kc * SB1 + n];
                uint32_t b1 = Bs[(kc + 4) * SB1 + n];
                mma_tf32(acc[0][nj], a[0], b0, b1);
                mma_tf32(acc[1][nj], a[1], b0, b1);
            }
        }
        __syncthreads();
    }

    float* O = (n0 < 256) ? outL : outR;
    int nb = n0 & 255;
#pragma unroll
    for (int mi = 0; mi < 2; mi++) {
        int r = m0 + warp_m * 32 + mi * 16 + (lane >> 2);
#pragma unroll
        for (int nj = 0; nj < 8; nj++) {
            int nc = nb + warp_n * 64 + nj * 8 + (lane & 3) * 2;
            if (r < M)
                *(float2*)&O[(size_t)r * 256 + nc] = make_float2(acc[mi][nj][0], acc[mi][nj][1]);
            if (r + 8 < M)
                *(float2*)&O[(size_t)(r + 8) * 256 + nc] = make_float2(acc[mi][nj][2], acc[mi][nj][3]);
        }
    }
}

// ---------------- layer-1 fused single-pass online-softmax attention ----------------
// warp per dst node; lane covers channels lane*8..lane*8+7 (head = lane>>3)
__global__ __launch_bounds__(256) void k_attn1(const float* __restrict__ att,
                                               const float* __restrict__ b1, int N)
{
    int gt = blockIdx.x * blockDim.x + threadIdx.x;
    int w = gt >> 5, lane = gt & 31;
    if (w >= N) return;
    int beg = g_offs[w], end = g_offs[w + 1];

    const float4* pxr = (const float4*)g_xr1 + (size_t)w * 64 + lane * 2;
    float4 r0 = pxr[0], r1 = pxr[1];
    const float4* pa = (const float4*)att + lane * 2;
    float4 at0 = pa[0], at1 = pa[1];

    float mx = -1e30f, dn = 0.f;
    float c0 = 0, c1 = 0, c2 = 0, c3 = 0, c4 = 0, c5 = 0, c6 = 0, c7 = 0;

    for (int p = beg; p < end; p++) {
        int src = g_src[p];
        const float4* pl = (const float4*)g_xl1 + (size_t)src * 64 + lane * 2;
        float4 a0 = pl[0], a1 = pl[1];
        float v, s = 0.f;
        v = a0.x + r0.x; s += fmaxf(v, 0.2f * v) * at0.x;
        v = a0.y + r0.y; s += fmaxf(v, 0.2f * v) * at0.y;
        v = a0.z + r0.z; s += fmaxf(v, 0.2f * v) * at0.z;
        v = a0.w + r0.w; s += fmaxf(v, 0.2f * v) * at0.w;
        v = a1.x + r1.x; s += fmaxf(v, 0.2f * v) * at1.x;
        v = a1.y + r1.y; s += fmaxf(v, 0.2f * v) * at1.y;
        v = a1.z + r1.z; s += fmaxf(v, 0.2f * v) * at1.z;
        v = a1.w + r1.w; s += fmaxf(v, 0.2f * v) * at1.w;
        s += __shfl_xor_sync(0xffffffffu, s, 4);
        s += __shfl_xor_sync(0xffffffffu, s, 2);
        s += __shfl_xor_sync(0xffffffffu, s, 1);
        // online softmax update (per-head; uniform within 8-lane group)
        float mnew = fmaxf(mx, s);
        float sc = __expf(mx - s) > 0.f ? expf(mx - mnew) : 0.f; // placeholder avoided below
        sc = expf(mx - mnew);
        float a = expf(s - mnew);
        dn = dn * sc + a;
        c0 = c0 * sc + a * a0.x; c1 = c1 * sc + a * a0.y;
        c2 = c2 * sc + a * a0.z; c3 = c3 * sc + a * a0.w;
        c4 = c4 * sc + a * a1.x; c5 = c5 * sc + a * a1.y;
        c6 = c6 * sc + a * a1.z; c7 = c7 * sc + a * a1.w;
        mx = mnew;
    }
    float inv = 1.f / (dn + 1e-16f);
    const float4* pb = (const float4*)b1 + lane * 2;
    float4 bb0 = pb[0], bb1 = pb[1];
    ((float4*)g_h1)[(size_t)w * 64 + lane * 2 + 0] =
        make_float4(c0 * inv + bb0.x, c1 * inv + bb0.y, c2 * inv + bb0.z, c3 * inv + bb0.w);
    ((float4*)g_h1)[(size_t)w * 64 + lane * 2 + 1] =
        make_float4(c4 * inv + bb1.x, c5 * inv + bb1.y, c6 * inv + bb1.z, c7 * inv + bb1.w);
}

// ---------------- batch-norm stats ----------------
__global__ __launch_bounds__(256) void k_bnstats(int N)
{
    int c = threadIdx.x;
    int r0 = blockIdx.x * 128;
    int rend = min(r0 + 128, N);
    float s = 0.f, s2 = 0.f;
    for (int r = r0; r < rend; r++) {
        float v = g_h1[(size_t)r * 256 + c];
        s += v; s2 += v * v;
    }
    atomicAdd(&g_bn[c], s);
    atomicAdd(&g_bn[256 + c], s2);
}

__global__ void k_bnfin(const float* __restrict__ gamma,
                        const float* __restrict__ beta, int N)
{
    int c = threadIdx.x;
    float invN = 1.f / (float)N;
    float mu = g_bn[c] * invN;
    float var = g_bn[256 + c] * invN - mu * mu;
    float rs = rsqrtf(var + 1e-5f);
    float s = gamma[c] * rs;
    g_bns[c] = s;
    g_bnt[c] = beta[c] - s * mu;
}

// ---------------- layer-2 fused BN+ELU + tf32 GEMM ----------------
#define SA2 36
#define SB2 88
__global__ __launch_bounds__(256) void k_gemm2_tc(float* __restrict__ xl2,
                                                  float* __restrict__ xr2, int M)
{
    __shared__ uint32_t As[128 * SA2];
    __shared__ uint32_t Bs[32 * SB2];
    int tid = threadIdx.x;
    int lane = tid & 31, wid = tid >> 5;
    int m0 = blockIdx.x * 128;
    float acc[10][4] = {};

    for (int k0 = 0; k0 < 256; k0 += 32) {
#pragma unroll
        for (int i = 0; i < 4; i++) {
            int f = tid + i * 256;
            int r = f >> 3, c4 = (f & 7) * 4;
            int gr = m0 + r;
            float4 v = make_float4(0.f, 0.f, 0.f, 0.f);
            if (gr < M) v = *(const float4*)&g_h1[(size_t)gr * 256 + k0 + c4];
            float4 s4 = *(const float4*)&g_bns[k0 + c4];
            float4 t4 = *(const float4*)&g_bnt[k0 + c4];
            float e0 = s4.x * v.x + t4.x; e0 = e0 > 0.f ? e0 : (expf(e0) - 1.f);
            float e1 = s4.y * v.y + t4.y; e1 = e1 > 0.f ? e1 : (expf(e1) - 1.f);
            float e2 = s4.z * v.z + t4.z; e2 = e2 > 0.f ? e2 : (expf(e2) - 1.f);
            float e3 = s4.w * v.w + t4.w; e3 = e3 > 0.f ? e3 : (expf(e3) - 1.f);
            uint4 u = make_uint4(f2tf32(e0), f2tf32(e1), f2tf32(e2), f2tf32(e3));
            *(uint4*)&As[r * SA2 + c4] = u;
        }
#pragma unroll
        for (int i = 0; i < 3; i++) {
            int f = tid + i * 256;
            if (f < 640) {
                int k = f / 20, n4 = (f % 20) * 4;
                float4 v = *(const float4*)&g_W2[(size_t)(k0 + k) * 80 + n4];
                uint4 u = make_uint4(f2tf32(v.x), f2tf32(v.y), f2tf32(v.z), f2tf32(v.w));
                *(uint4*)&Bs[k * SB2 + n4] = u;
            }
        }
        __syncthreads();
#pragma unroll
        for (int ks = 0; ks < 4; ks++) {
            int kc = ks * 8 + (lane & 3);
            int r = wid * 16 + (lane >> 2);
            uint32_t a[4];
            a[0] = As[r * SA2 + kc];
            a[1] = As[(r + 8) * SA2 + kc];
            a[2] = As[r * SA2 + kc + 4];
            a[3] = As[(r + 8) * SA2 + kc + 4];
#pragma unroll
            for (int nj = 0; nj < 10; nj++) {
                int n = nj * 8 + (lane >> 2);
                uint32_t b0 = Bs[kc * SB2 + n];
                uint32_t b1 = Bs[(kc + 4) * SB2 + n];
                mma_tf32(acc[nj], a, b0, b1);
            }
        }
        __syncthreads();
    }

    int r = m0 + wid * 16 + (lane >> 2);
#pragma unroll
    for (int nj = 0; nj < 10; nj++) {
        int col = nj * 8 + (lane & 3) * 2;
        float* O  = (col < 40) ? xl2 : xr2;
        int cc = (col < 40) ? col : col - 40;
        if (r < M)
            *(float2*)&O[(size_t)r * 40 + cc] = make_float2(acc[nj][0], acc[nj][1]);
        if (r + 8 < M)
            *(float2*)&O[(size_t)(r + 8) * 40 + cc] = make_float2(acc[nj][2], acc[nj][3]);
    }
}

// ---------------- layer-2 fused single-pass online-softmax attention ----------------
// warp per dst node; 4 edges per iteration; 8-lane group per edge, 5 channels per lane
__global__ __launch_bounds__(256) void k_attn2(const float* __restrict__ att2,
                                               const float* __restrict__ b2,
                                               float* __restrict__ out, int N)
{
    int gt = blockIdx.x * blockDim.x + threadIdx.x;
    int w = gt >> 5, lane = gt & 31;
    if (w >= N) return;
    int beg = g_offs[w], end = g_offs[w + 1];
    int sub = lane >> 3, l8 = lane & 7;

    float xr[5], at[5];
#pragma unroll
    for (int j = 0; j < 5; j++) {
        int c = l8 * 5 + j;
        xr[j] = g_xr2[(size_t)w * 40 + c];
        at[j] = att2[c];
    }

    float mx = -1e30f, dn = 0.f;
    float acc[5] = {};

    for (int p0 = beg; p0 < end; p0 += 4) {
        int p = p0 + sub;
        bool valid = (p < end);
        int src = g_src[valid ? p : beg];
        float xls[5];
        float s = 0.f;
#pragma unroll
        for (int j = 0; j < 5; j++) {
            xls[j] = g_xl2[(size_t)src * 40 + l8 * 5 + j];
            float v = xls[j] + xr[j];
            s += fmaxf(v, 0.2f * v) * at[j];
        }
        s += __shfl_xor_sync(0xffffffffu, s, 4);
        s += __shfl_xor_sync(0xffffffffu, s, 2);
        s += __shfl_xor_sync(0xffffffffu, s, 1);
        if (!valid) s = -1e30f;
        float mnew = fmaxf(mx, s);
        float sc = expf(mx - mnew);
        float a  = valid ? expf(s - mnew) : 0.f;
        dn = dn * sc + a;
#pragma unroll
        for (int j = 0; j < 5; j++) acc[j] = acc[j] * sc + a * xls[j];
        mx = mnew;
    }

    // merge the 4 sub-group partials (offsets 8, 16)
#pragma unroll
    for (int off = 8; off <= 16; off <<= 1) {
        float mo  = __shfl_xor_sync(0xffffffffu, mx, off);
        float dno = __shfl_xor_sync(0xffffffffu, dn, off);
        float ao[5];
#pragma unroll
        for (int j = 0; j < 5; j++) ao[j] = __shfl_xor_sync(0xffffffffu, acc[j], off);
        float m = fmaxf(mx, mo);
        float f1 = expf(mx - m), f2 = expf(mo - m);
        dn = dn * f1 + dno * f2;
#pragma unroll
        for (int j = 0; j < 5; j++) acc[j] = acc[j] * f1 + ao[j] * f2;
        mx = m;
    }

    float inv = 1.f / (dn + 1e-16f);
    if (sub == 0) {
#pragma unroll
        for (int j = 0; j < 5; j++) {
            int c = l8 * 5 + j;
            out[(size_t)w * 40 + c] = acc[j] * inv + b2[c];
        }
    }
}

// ---------------- host launcher ----------------
extern "C" void kernel_launch(void* const* d_in, const int* in_sizes, int n_in,
                              void* d_out, int out_size)
{
    const float* x      = (const float*)d_in[0];
    const int*   ei     = (const int*)  d_in[1];
    const float* Wl1    = (const float*)d_in[2];
    const float* Wr1    = (const float*)d_in[3];
    const float* att1   = (const float*)d_in[4];
    const float* b1     = (const float*)d_in[5];
    const float* gamma1 = (const float*)d_in[6];
    const float* beta1  = (const float*)d_in[7];
    const float* Wl2    = (const float*)d_in[8];
    const float* Wr2    = (const float*)d_in[9];
    const float* att2   = (const float*)d_in[10];
    const float* b2     = (const float*)d_in[11];
    float* out = (float*)d_out;

    int N = in_sizes[0] / 128;
    int E = in_sizes[1] / 2;
    int ET = E + N;

    void *pxl1, *pxr1, *pxl2, *pxr2;
    cudaGetSymbolAddress(&pxl1, g_xl1);
    cudaGetSymbolAddress(&pxr1, g_xr1);
    cudaGetSymbolAddress(&pxl2, g_xl2);
    cudaGetSymbolAddress(&pxr2, g_xr2);

    k_zero<<<(N + 256) / 256, 256>>>(N);
    k_count<<<(ET + 255) / 256, 256>>>(ei, E, N);
    k_scan<<<1, 1024>>>(N);
    k_fill<<<(ET + 255) / 256, 256>>>(ei, E, N);
    k_w1cat<<<(128 * 512 + 255) / 256, 256>>>(Wl1, Wr1);
    k_w2cat<<<(256 * 80 + 255) / 256, 256>>>(Wl2, Wr2);

    dim3 g1(4, (N + 127) / 128);
    k_gemm1_tc<<<g1, 256>>>(x, (float*)pxl1, (float*)pxr1, N);

    k_attn1<<<(N + 7) / 8, 256>>>(att1, b1, N);

    k_bnstats<<<(N + 127) / 128, 256>>>(N);
    k_bnfin<<<1, 256>>>(gamma1, beta1, N);

    k_gemm2_tc<<<(N + 127) / 128, 256>>>((float*)pxl2, (float*)pxr2, N);

    k_attn2<<<(N + 7) / 8, 256>>>(att2, b2, out, N);
}